// round 1
// baseline (speedup 1.0000x reference)
#include <cuda_runtime.h>
#include <math.h>

// Problem constants (fixed shapes for this problem)
#define BB    2
#define SEQ   2048
#define DIM   1024
#define HEADS 16
#define DH    64
#define MTOT  (BB * SEQ)   // 4096 rows

// ---------------------------------------------------------------------------
// Scratch (device globals: allocation-free, harness-safe)
// Q/K/V stored as [B, H, S, DH]; O stored as [B*S, DIM]
// ---------------------------------------------------------------------------
__device__ float g_Q[(size_t)BB * HEADS * SEQ * DH];
__device__ float g_K[(size_t)BB * HEADS * SEQ * DH];
__device__ float g_V[(size_t)BB * HEADS * SEQ * DH];
__device__ float g_O[(size_t)MTOT * DIM];

// ---------------------------------------------------------------------------
// SGEMM: C[M=4096, N=1024] = A[4096,1024] @ B[1024,1024], fp32.
// 128x128 block tile, BK=8, 256 threads, 8x8 register tile.
// MODE 0: plain row-major store. MODE 1: scatter into [B,H,S,DH] layout.
// ---------------------------------------------------------------------------
template <int MODE>
__device__ __forceinline__ void sgemm_body(const float* __restrict__ A,
                                           const float* __restrict__ B,
                                           float* __restrict__ C) {
    constexpr int N = DIM;
    constexpr int K = DIM;

    __shared__ float As[8][128];   // transposed A tile: As[k][m]
    __shared__ float Bs[8][128];   // Bs[k][n]

    const int tid  = threadIdx.x;
    const int m0   = blockIdx.y * 128;
    const int n0   = blockIdx.x * 128;
    const int trow = tid >> 4;          // 0..15
    const int tcol = tid & 15;          // 0..15
    const int aRow = tid >> 1;          // 0..127
    const int aCol = (tid & 1) * 4;     // 0 or 4
    const int bRow = tid >> 5;          // 0..7
    const int bCol = (tid & 31) * 4;    // 0..124

    const float* Aptr = A + (size_t)m0 * K;
    const float* Bptr = B + n0;

    float acc[8][8];
#pragma unroll
    for (int i = 0; i < 8; i++)
#pragma unroll
        for (int j = 0; j < 8; j++) acc[i][j] = 0.0f;

    for (int k0 = 0; k0 < K; k0 += 8) {
        float4 av = *(const float4*)(Aptr + (size_t)aRow * K + (k0 + aCol));
        float4 bv = *(const float4*)(Bptr + (size_t)(k0 + bRow) * N + bCol);
        As[aCol + 0][aRow] = av.x;
        As[aCol + 1][aRow] = av.y;
        As[aCol + 2][aRow] = av.z;
        As[aCol + 3][aRow] = av.w;
        *(float4*)(&Bs[bRow][bCol]) = bv;
        __syncthreads();

#pragma unroll
        for (int kk = 0; kk < 8; kk++) {
            float ar[8], br[8];
            *(float4*)(ar)     = *(const float4*)(&As[kk][trow * 8]);
            *(float4*)(ar + 4) = *(const float4*)(&As[kk][trow * 8 + 4]);
            *(float4*)(br)     = *(const float4*)(&Bs[kk][tcol * 8]);
            *(float4*)(br + 4) = *(const float4*)(&Bs[kk][tcol * 8 + 4]);
#pragma unroll
            for (int i = 0; i < 8; i++)
#pragma unroll
                for (int j = 0; j < 8; j++) acc[i][j] += ar[i] * br[j];
        }
        __syncthreads();
    }

    // Epilogue
#pragma unroll
    for (int i = 0; i < 8; i++) {
        const int m = m0 + trow * 8 + i;
#pragma unroll
        for (int jg = 0; jg < 2; jg++) {
            const int n = n0 + tcol * 8 + jg * 4;
            float4 o;
            o.x = acc[i][jg * 4 + 0];
            o.y = acc[i][jg * 4 + 1];
            o.z = acc[i][jg * 4 + 2];
            o.w = acc[i][jg * 4 + 3];
            size_t idx;
            if (MODE == 0) {
                idx = (size_t)m * N + n;
            } else {
                const int b = m >> 11;          // m / SEQ
                const int s = m & (SEQ - 1);
                const int h = n >> 6;           // n / DH
                const int d = n & (DH - 1);
                idx = ((size_t)(b * HEADS + h) * SEQ + s) * DH + d;
            }
            *(float4*)(&C[idx]) = o;
        }
    }
}

template <int WHICH>
__global__ __launch_bounds__(256) void qkv_gemm(const float* __restrict__ x,
                                                const float* __restrict__ W) {
    float* C = (WHICH == 0) ? g_Q : (WHICH == 1) ? g_K : g_V;
    sgemm_body<1>(x, W, C);
}

__global__ __launch_bounds__(256) void out_gemm(const float* __restrict__ W,
                                                float* __restrict__ out) {
    sgemm_body<0>(g_O, W, out);
}

// ---------------------------------------------------------------------------
// Flash attention (fp32, causal). Block = (q-tile of 64 rows, head, batch).
// KV processed in tiles of 32. 256 threads.
//  Score phase: thread -> 2 q-rows x 4 kc   (Qts/Kts transposed in smem)
//  Softmax+PV : thread -> 1 q-row  x 16 dv  (dv interleaved part*4+16g)
// ---------------------------------------------------------------------------
__global__ __launch_bounds__(256) void attn_kernel(float* __restrict__ Odummy) {
    __shared__ float Qts[64][66];   // [d][qrow]  pad 66: float2 loads aligned
    __shared__ float Kts[64][33];   // [d][kcol]  pad 33: conflict-free stores
    __shared__ float Vs[32][68];    // [kcol][d]  pad 68: float4 aligned
    __shared__ float Ss[64][36];    // [qrow][kcol] pad 36

    const int qt = blockIdx.x;
    const int h  = blockIdx.y;
    const int b  = blockIdx.z;
    const size_t headoff = (size_t)(b * HEADS + h) * SEQ * DH;
    const float* Qh = g_Q + headoff;
    const float* Kh = g_K + headoff;
    const float* Vh = g_V + headoff;

    const int tid = threadIdx.x;
    const int q0  = qt * 64;

    // Load Q tile transposed: Qts[d][r]
    {
        const int d  = tid & 63;
        const int qg = tid >> 6;
#pragma unroll
        for (int i = 0; i < 16; i++) {
            const int r = qg * 16 + i;
            Qts[d][r] = Qh[(size_t)(q0 + r) * DH + d];
        }
    }

    const int row  = tid >> 2;       // 0..63  (softmax/PV mapping)
    const int part = tid & 3;        // 0..3
    const int r0   = (tid >> 3) * 2; // score mapping: rows r0, r0+1
    const int c0   = (tid & 7) * 4;  // score mapping: kc c0..c0+3

    float acc[16];
#pragma unroll
    for (int i = 0; i < 16; i++) acc[i] = 0.0f;
    float m_i = -INFINITY;
    float l_i = 0.0f;

    const int nkt = 2 * (qt + 1);   // causal: k-tiles 0..2qt+1
    for (int kt = 0; kt < nkt; kt++) {
        const int k0 = kt * 32;
        __syncthreads();   // previous iteration's readers done

        // Load K tile transposed: Kts[d][kc]
        {
            const int d  = tid & 63;
            const int kg = tid >> 6;
#pragma unroll
            for (int i = 0; i < 8; i++) {
                const int r = kg * 8 + i;
                Kts[d][r] = Kh[(size_t)(k0 + r) * DH + d];
            }
        }
        // Load V tile row-major: Vs[kc][d]
        {
            const int r = tid >> 4;
            const int c = (tid & 15) * 4;
#pragma unroll
            for (int rr = 0; rr < 2; rr++) {
                const int vr = r + rr * 16;
                float4 vv = *(const float4*)(Vh + (size_t)(k0 + vr) * DH + c);
                Vs[vr][c + 0] = vv.x;
                Vs[vr][c + 1] = vv.y;
                Vs[vr][c + 2] = vv.z;
                Vs[vr][c + 3] = vv.w;
            }
        }
        __syncthreads();

        // ---- Phase A: scores (2 rows x 4 kc per thread) ----
        float sc0[4] = {0.f, 0.f, 0.f, 0.f};
        float sc1[4] = {0.f, 0.f, 0.f, 0.f};
#pragma unroll 8
        for (int d = 0; d < 64; d++) {
            const float2 q2 = *(const float2*)(&Qts[d][r0]);
#pragma unroll
            for (int j = 0; j < 4; j++) {
                const float kv = Kts[d][c0 + j];
                sc0[j] += q2.x * kv;
                sc1[j] += q2.y * kv;
            }
        }
        {
            float4 o0, o1;
            float* p0 = &o0.x;
            float* p1 = &o1.x;
#pragma unroll
            for (int j = 0; j < 4; j++) {
                const int kg = k0 + c0 + j;
                p0[j] = (kg <= q0 + r0)     ? sc0[j] * 0.125f : -INFINITY;
                p1[j] = (kg <= q0 + r0 + 1) ? sc1[j] * 0.125f : -INFINITY;
            }
            *(float4*)(&Ss[r0][c0])     = o0;
            *(float4*)(&Ss[r0 + 1][c0]) = o1;
        }
        __syncwarp();   // each warp owns its 8 rows in both mappings

        // ---- Phase B: online softmax (1 row per 4 lanes) ----
        float s8[8];
        float tmax = -INFINITY;
#pragma unroll
        for (int jj = 0; jj < 8; jj++) {
            s8[jj] = Ss[row][part + 4 * jj];
            tmax   = fmaxf(tmax, s8[jj]);
        }
        tmax = fmaxf(tmax, __shfl_xor_sync(0xffffffffu, tmax, 1));
        tmax = fmaxf(tmax, __shfl_xor_sync(0xffffffffu, tmax, 2));
        const float m_new = fmaxf(m_i, tmax);
        const float corr  = __expf(m_i - m_new);
        float lsum = 0.0f;
#pragma unroll
        for (int jj = 0; jj < 8; jj++) {
            const float p = __expf(s8[jj] - m_new);
            Ss[row][part + 4 * jj] = p;
            lsum += p;
        }
        lsum += __shfl_xor_sync(0xffffffffu, lsum, 1);
        lsum += __shfl_xor_sync(0xffffffffu, lsum, 2);
        l_i = l_i * corr + lsum;
        m_i = m_new;
#pragma unroll
        for (int i = 0; i < 16; i++) acc[i] *= corr;
        __syncwarp();

        // ---- PV: acc[g*4+j] over dv = part*4 + 16g + j ----
#pragma unroll 4
        for (int kc = 0; kc < 32; kc++) {
            const float p = Ss[row][kc];
#pragma unroll
            for (int g = 0; g < 4; g++) {
                const float4 v = *(const float4*)(&Vs[kc][part * 4 + 16 * g]);
                acc[g * 4 + 0] += p * v.x;
                acc[g * 4 + 1] += p * v.y;
                acc[g * 4 + 2] += p * v.z;
                acc[g * 4 + 3] += p * v.w;
            }
        }
    }

    // Epilogue: O[b, s, h*64 + dv]
    const float inv = 1.0f / l_i;
    const size_t obase =
        ((size_t)b * SEQ + (q0 + row)) * DIM + h * DH;
#pragma unroll
    for (int g = 0; g < 4; g++) {
        float4 o;
        o.x = acc[g * 4 + 0] * inv;
        o.y = acc[g * 4 + 1] * inv;
        o.z = acc[g * 4 + 2] * inv;
        o.w = acc[g * 4 + 3] * inv;
        *(float4*)(&g_O[obase + part * 4 + 16 * g]) = o;
    }
    (void)Odummy;
}

// ---------------------------------------------------------------------------
// kernel_launch: x, mask(unused; causal is known), Wq, Wk, Wv, Wo -> out
// ---------------------------------------------------------------------------
extern "C" void kernel_launch(void* const* d_in, const int* in_sizes, int n_in,
                              void* d_out, int out_size) {
    const float* x  = (const float*)d_in[0];
    // d_in[1] = mask (int32, causal tril) — structure known, unused
    const float* Wq = (const float*)d_in[2];
    const float* Wk = (const float*)d_in[3];
    const float* Wv = (const float*)d_in[4];
    const float* Wo = (const float*)d_in[5];
    float* out = (float*)d_out;

    const dim3 gg(DIM / 128, MTOT / 128);   // (8, 32)
    const dim3 gb(256);

    qkv_gemm<0><<<gg, gb>>>(x, Wq);
    qkv_gemm<1><<<gg, gb>>>(x, Wk);
    qkv_gemm<2><<<gg, gb>>>(x, Wv);

    attn_kernel<<<dim3(SEQ / 64, HEADS, BB), 256>>>(nullptr);

    out_gemm<<<gg, gb>>>(Wo, out);
}

// round 3
// speedup vs baseline: 1.3559x; 1.3559x over previous
#include <cuda_runtime.h>
#include <cuda_bf16.h>
#include <math.h>
#include <stdint.h>

#define BB    2
#define SEQ   2048
#define DIM   1024
#define HEADS 16
#define DH    64
#define MTOT  (BB * SEQ)   // 4096

// ---------------------------------------------------------------------------
// Scratch (device globals: allocation-free, harness-safe)
// ---------------------------------------------------------------------------
__device__ float g_Q[(size_t)MTOT * DIM];   // [B,H,S,DH]
__device__ float g_K[(size_t)MTOT * DIM];
__device__ float g_V[(size_t)MTOT * DIM];
__device__ __nv_bfloat16 gX0[(size_t)MTOT * DIM];     // x split hi  [m][k]
__device__ __nv_bfloat16 gX1[(size_t)MTOT * DIM];     // x split lo
__device__ __nv_bfloat16 gW0[(size_t)4 * DIM * DIM];  // W^T split hi [w][n][k]
__device__ __nv_bfloat16 gW1[(size_t)4 * DIM * DIM];  // W^T split lo
__device__ __nv_bfloat16 gO0[(size_t)MTOT * DIM];     // attn out split hi
__device__ __nv_bfloat16 gO1[(size_t)MTOT * DIM];     // attn out split lo

// ---------------------------------------------------------------------------
// Portable PTX helpers (sm_80+ baseline: ldmatrix / mma.sync / cp.async)
// ---------------------------------------------------------------------------
__device__ __forceinline__ uint32_t smem_u32(const void* p) {
    uint32_t a;
    asm("{ .reg .u64 t; cvta.to.shared.u64 t, %1; cvt.u32.u64 %0, t; }"
        : "=r"(a) : "l"(p));
    return a;
}

__device__ __forceinline__ void ldm_x4(uint32_t* r, uint32_t addr) {
    asm volatile("ldmatrix.sync.aligned.m8n8.x4.shared.b16 {%0,%1,%2,%3}, [%4];"
                 : "=r"(r[0]), "=r"(r[1]), "=r"(r[2]), "=r"(r[3]) : "r"(addr));
}

__device__ __forceinline__ void mma16816(float* d, const uint32_t* a,
                                         const uint32_t* b) {
    asm volatile(
        "mma.sync.aligned.m16n8k16.row.col.f32.bf16.bf16.f32 "
        "{%0,%1,%2,%3}, {%4,%5,%6,%7}, {%8,%9}, {%0,%1,%2,%3};"
        : "+f"(d[0]), "+f"(d[1]), "+f"(d[2]), "+f"(d[3])
        : "r"(a[0]), "r"(a[1]), "r"(a[2]), "r"(a[3]), "r"(b[0]), "r"(b[1]));
}

__device__ __forceinline__ void cp16(uint32_t s, const void* g) {
    asm volatile("cp.async.cg.shared.global [%0], [%1], 16;" :: "r"(s), "l"(g));
}

// ---------------------------------------------------------------------------
// HMMA bf16x3 GEMM: C[m][n] = sum_k A[m][k]*W[k][n]
// Block 128x128, BK=32, 8 warps (4m x 2n), warp tile 32x64.
// Smem rows padded to 80B -> ldmatrix conflict-free.
// MODE 1: A=gX*, B=gW[z], scatter into g_Q/g_K/g_V (z=0/1/2)
// MODE 0: A=gO*, B=gW[3], row-major fp32 store to outp
// ---------------------------------------------------------------------------
#define AST   80          // smem row stride bytes (32 bf16 data + pad)
#define ARR   10240       // one 128-row array (128*80)
#define STG   40960       // one stage: A0,A1,B0,B1
#define SMEM_DYN (2 * STG)
#define NSLAB (DIM / 32)  // 32

template <int MODE>
__global__ __launch_bounds__(256) void hmma_gemm(float* __restrict__ outp) {
    extern __shared__ char smem_raw[];
    const uint32_t sbase = smem_u32(smem_raw);
    const int tid  = threadIdx.x;
    const int lane = tid & 31;
    const int wid  = tid >> 5;
    const int z    = blockIdx.z;
    const int m0   = blockIdx.y * 128;
    const int n0   = blockIdx.x * 128;

    const __nv_bfloat16* A0g = (MODE == 1) ? gX0 : gO0;
    const __nv_bfloat16* A1g = (MODE == 1) ? gX1 : gO1;
    const size_t woff = (MODE == 1) ? (size_t)z * DIM * DIM : (size_t)3 * DIM * DIM;
    const __nv_bfloat16* B0g = gW0 + woff;
    const __nv_bfloat16* B1g = gW1 + woff;

    const int ldr = tid >> 2;        // 0..63  (load row base, 2 sets of rows)
    const int ldc = tid & 3;         // uint4 index within 64B row

    float acc[2][8][4];
#pragma unroll
    for (int mi = 0; mi < 2; mi++)
#pragma unroll
        for (int ni = 0; ni < 8; ni++)
#pragma unroll
            for (int u = 0; u < 4; u++) acc[mi][ni][u] = 0.0f;

    const int wm = (wid & 3) * 32;
    const int wn = (wid >> 2) * 64;
    const int lrow  = lane & 15;
    const int lcolb = (lane >> 4) * 16;

    // slab loader: 4 arrays x 128 rows x 4 uint4, 8 cp.async per thread
#define ISSUE_SLAB(s) do {                                                    \
        const int _st = (s) & 1;                                              \
        const int _k0 = (s) * 32;                                             \
        _Pragma("unroll")                                                     \
        for (int t = 0; t < 2; t++) {                                         \
            const int r = ldr + t * 64;                                       \
            const size_t ga = (size_t)(m0 + r) * DIM + _k0 + ldc * 8;         \
            const uint32_t sa = sbase + _st * STG + r * AST + ldc * 16;       \
            cp16(sa, A0g + ga);                                               \
            cp16(sa + ARR, A1g + ga);                                         \
            const size_t gb = (size_t)(n0 + r) * DIM + _k0 + ldc * 8;         \
            const uint32_t sb = sbase + _st * STG + 2 * ARR + r * AST + ldc * 16; \
            cp16(sb, B0g + gb);                                               \
            cp16(sb + ARR, B1g + gb);                                         \
        }                                                                     \
        asm volatile("cp.async.commit_group;" ::: "memory");                  \
    } while (0)

    ISSUE_SLAB(0);
    for (int s = 0; s < NSLAB; s++) {
        if (s + 1 < NSLAB) {
            ISSUE_SLAB(s + 1);
            asm volatile("cp.async.wait_group 1;" ::: "memory");
        } else {
            asm volatile("cp.async.wait_group 0;" ::: "memory");
        }
        __syncthreads();

        const uint32_t stoff = (uint32_t)(s & 1) * STG;
#pragma unroll
        for (int j = 0; j < 2; j++) {
            const uint32_t kb = j * 32 + lcolb;
            uint32_t a0f[2][4], a1f[2][4];
#pragma unroll
            for (int mi = 0; mi < 2; mi++) {
                const uint32_t ad =
                    sbase + stoff + (wm + mi * 16 + lrow) * AST + kb;
                ldm_x4(a0f[mi], ad);
                ldm_x4(a1f[mi], ad + ARR);
            }
            uint32_t b0f[8][2], b1f[8][2];
#pragma unroll
            for (int nt = 0; nt < 4; nt++) {
                const uint32_t bd =
                    sbase + stoff + 2 * ARR + (wn + nt * 16 + lrow) * AST + kb;
                uint32_t r4[4];
                ldm_x4(r4, bd);
                b0f[nt * 2][0]     = r4[0]; b0f[nt * 2][1]     = r4[2];
                b0f[nt * 2 + 1][0] = r4[1]; b0f[nt * 2 + 1][1] = r4[3];
                ldm_x4(r4, bd + ARR);
                b1f[nt * 2][0]     = r4[0]; b1f[nt * 2][1]     = r4[2];
                b1f[nt * 2 + 1][0] = r4[1]; b1f[nt * 2 + 1][1] = r4[3];
            }
#pragma unroll
            for (int mi = 0; mi < 2; mi++)
#pragma unroll
                for (int ni = 0; ni < 8; ni++) {
                    mma16816(acc[mi][ni], a0f[mi], b0f[ni]);
                    mma16816(acc[mi][ni], a0f[mi], b1f[ni]);
                    mma16816(acc[mi][ni], a1f[mi], b0f[ni]);
                }
        }
        __syncthreads();
    }

    // Epilogue: d-frag lane mapping -> float2 stores
#pragma unroll
    for (int mi = 0; mi < 2; mi++)
#pragma unroll
        for (int ni = 0; ni < 8; ni++) {
            const int cc = n0 + wn + ni * 8 + (lane & 3) * 2;
#pragma unroll
            for (int h2 = 0; h2 < 2; h2++) {
                const int m = m0 + wm + mi * 16 + (lane >> 2) + h2 * 8;
                float2 o = make_float2(acc[mi][ni][h2 * 2],
                                       acc[mi][ni][h2 * 2 + 1]);
                if (MODE == 0) {
                    *(float2*)(outp + (size_t)m * DIM + cc) = o;
                } else {
                    const int b = m >> 11, sq = m & (SEQ - 1);
                    const int h = cc >> 6, d0 = cc & 63;
                    float* G = (z == 0) ? g_Q : (z == 1) ? g_K : g_V;
                    *(float2*)(G + ((size_t)(b * HEADS + h) * SEQ + sq) * DH + d0) = o;
                }
            }
        }
}

// ---------------------------------------------------------------------------
// Prep: split x into bf16 hi/lo
// ---------------------------------------------------------------------------
__global__ __launch_bounds__(256) void split_x_kernel(const float* __restrict__ x) {
    const int i = blockIdx.x * 256 + threadIdx.x;
    const float4 v = ((const float4*)x)[i];
    union { __nv_bfloat16 h[4]; uint2 u; } H, L;
    const float f[4] = {v.x, v.y, v.z, v.w};
#pragma unroll
    for (int j = 0; j < 4; j++) {
        H.h[j] = __float2bfloat16_rn(f[j]);
        L.h[j] = __float2bfloat16_rn(f[j] - __bfloat162float(H.h[j]));
    }
    *(uint2*)(gX0 + (size_t)i * 4) = H.u;
    *(uint2*)(gX1 + (size_t)i * 4) = L.u;
}

// Prep: transpose + split weights. W[k][n] -> Wt[n][k] bf16 hi/lo.
__global__ __launch_bounds__(256) void prep_w_kernel(const float* __restrict__ Wq,
                                                     const float* __restrict__ Wk,
                                                     const float* __restrict__ Wv,
                                                     const float* __restrict__ Wo) {
    __shared__ float tile[32][33];
    const int z = blockIdx.z;
    const float* W = (z == 0) ? Wq : (z == 1) ? Wk : (z == 2) ? Wv : Wo;
    __nv_bfloat16* T0 = gW0 + (size_t)z * DIM * DIM;
    __nv_bfloat16* T1 = gW1 + (size_t)z * DIM * DIM;
    const int n0 = blockIdx.x * 32, k0 = blockIdx.y * 32;
    const int tx = threadIdx.x & 31, ty = threadIdx.x >> 5;   // 32 x 8
#pragma unroll
    for (int i = 0; i < 4; i++)
        tile[ty + 8 * i][tx] = W[(size_t)(k0 + ty + 8 * i) * DIM + n0 + tx];
    __syncthreads();
#pragma unroll
    for (int i = 0; i < 4; i++) {
        const int n = n0 + ty + 8 * i;
        const float v = tile[tx][ty + 8 * i];
        const __nv_bfloat16 hi = __float2bfloat16_rn(v);
        T0[(size_t)n * DIM + k0 + tx] = hi;
        T1[(size_t)n * DIM + k0 + tx] = __float2bfloat16_rn(v - __bfloat162float(hi));
    }
}

// ---------------------------------------------------------------------------
// Flash attention (fp32, causal); epilogue writes split bf16 into gO0/gO1
// ---------------------------------------------------------------------------
__global__ __launch_bounds__(256) void attn_kernel() {
    __shared__ float Qts[64][66];
    __shared__ float Kts[64][33];
    __shared__ float Vs[32][68];
    __shared__ float Ss[64][36];

    const int qt = blockIdx.x;
    const int h  = blockIdx.y;
    const int b  = blockIdx.z;
    const size_t headoff = (size_t)(b * HEADS + h) * SEQ * DH;
    const float* Qh = g_Q + headoff;
    const float* Kh = g_K + headoff;
    const float* Vh = g_V + headoff;

    const int tid = threadIdx.x;
    const int q0  = qt * 64;

    {
        const int d  = tid & 63;
        const int qg = tid >> 6;
#pragma unroll
        for (int i = 0; i < 16; i++) {
            const int r = qg * 16 + i;
            Qts[d][r] = Qh[(size_t)(q0 + r) * DH + d];
        }
    }

    const int row  = tid >> 2;
    const int part = tid & 3;
    const int r0   = (tid >> 3) * 2;
    const int c0   = (tid & 7) * 4;

    float acc[16];
#pragma unroll
    for (int i = 0; i < 16; i++) acc[i] = 0.0f;
    float m_i = -INFINITY;
    float l_i = 0.0f;

    const int nkt = 2 * (qt + 1);
    for (int kt = 0; kt < nkt; kt++) {
        const int k0 = kt * 32;
        __syncthreads();
        {
            const int d  = tid & 63;
            const int kg = tid >> 6;
#pragma unroll
            for (int i = 0; i < 8; i++) {
                const int r = kg * 8 + i;
                Kts[d][r] = Kh[(size_t)(k0 + r) * DH + d];
            }
        }
        {
            const int r = tid >> 4;
            const int c = (tid & 15) * 4;
#pragma unroll
            for (int rr = 0; rr < 2; rr++) {
                const int vr = r + rr * 16;
                float4 vv = *(const float4*)(Vh + (size_t)(k0 + vr) * DH + c);
                Vs[vr][c + 0] = vv.x;
                Vs[vr][c + 1] = vv.y;
                Vs[vr][c + 2] = vv.z;
                Vs[vr][c + 3] = vv.w;
            }
        }
        __syncthreads();

        float sc0[4] = {0.f, 0.f, 0.f, 0.f};
        float sc1[4] = {0.f, 0.f, 0.f, 0.f};
#pragma unroll 8
        for (int d = 0; d < 64; d++) {
            const float2 q2 = *(const float2*)(&Qts[d][r0]);
#pragma unroll
            for (int j = 0; j < 4; j++) {
                const float kv = Kts[d][c0 + j];
                sc0[j] += q2.x * kv;
                sc1[j] += q2.y * kv;
            }
        }
        {
            float4 o0, o1;
            float* p0 = &o0.x;
            float* p1 = &o1.x;
#pragma unroll
            for (int j = 0; j < 4; j++) {
                const int kg = k0 + c0 + j;
                p0[j] = (kg <= q0 + r0)     ? sc0[j] * 0.125f : -INFINITY;
                p1[j] = (kg <= q0 + r0 + 1) ? sc1[j] * 0.125f : -INFINITY;
            }
            *(float4*)(&Ss[r0][c0])     = o0;
            *(float4*)(&Ss[r0 + 1][c0]) = o1;
        }
        __syncwarp();

        float s8[8];
        float tmax = -INFINITY;
#pragma unroll
        for (int jj = 0; jj < 8; jj++) {
            s8[jj] = Ss[row][part + 4 * jj];
            tmax   = fmaxf(tmax, s8[jj]);
        }
        tmax = fmaxf(tmax, __shfl_xor_sync(0xffffffffu, tmax, 1));
        tmax = fmaxf(tmax, __shfl_xor_sync(0xffffffffu, tmax, 2));
        const float m_new = fmaxf(m_i, tmax);
        const float corr  = __expf(m_i - m_new);
        float lsum = 0.0f;
#pragma unroll
        for (int jj = 0; jj < 8; jj++) {
            const float p = __expf(s8[jj] - m_new);
            Ss[row][part + 4 * jj] = p;
            lsum += p;
        }
        lsum += __shfl_xor_sync(0xffffffffu, lsum, 1);
        lsum += __shfl_xor_sync(0xffffffffu, lsum, 2);
        l_i = l_i * corr + lsum;
        m_i = m_new;
#pragma unroll
        for (int i = 0; i < 16; i++) acc[i] *= corr;
        __syncwarp();

#pragma unroll 4
        for (int kc = 0; kc < 32; kc++) {
            const float p = Ss[row][kc];
#pragma unroll
            for (int g = 0; g < 4; g++) {
                const float4 v = *(const float4*)(&Vs[kc][part * 4 + 16 * g]);
                acc[g * 4 + 0] += p * v.x;
                acc[g * 4 + 1] += p * v.y;
                acc[g * 4 + 2] += p * v.z;
                acc[g * 4 + 3] += p * v.w;
            }
        }
    }

    const float inv = 1.0f / l_i;
    const size_t obase = ((size_t)b * SEQ + (q0 + row)) * DIM + h * DH;
#pragma unroll
    for (int g = 0; g < 4; g++) {
        const float o[4] = {acc[g * 4 + 0] * inv, acc[g * 4 + 1] * inv,
                            acc[g * 4 + 2] * inv, acc[g * 4 + 3] * inv};
        union { __nv_bfloat16 h4[4]; uint2 u; } H, L;
#pragma unroll
        for (int j = 0; j < 4; j++) {
            H.h4[j] = __float2bfloat16_rn(o[j]);
            L.h4[j] = __float2bfloat16_rn(o[j] - __bfloat162float(H.h4[j]));
        }
        const size_t off = obase + part * 4 + 16 * g;
        *(uint2*)(gO0 + off) = H.u;
        *(uint2*)(gO1 + off) = L.u;
    }
}

// ---------------------------------------------------------------------------
// kernel_launch
// ---------------------------------------------------------------------------
extern "C" void kernel_launch(void* const* d_in, const int* in_sizes, int n_in,
                              void* d_out, int out_size) {
    const float* x  = (const float*)d_in[0];
    // d_in[1] = causal mask (structure known, unused)
    const float* Wq = (const float*)d_in[2];
    const float* Wk = (const float*)d_in[3];
    const float* Wv = (const float*)d_in[4];
    const float* Wo = (const float*)d_in[5];
    float* out = (float*)d_out;

    cudaFuncSetAttribute(hmma_gemm<0>, cudaFuncAttributeMaxDynamicSharedMemorySize, SMEM_DYN);
    cudaFuncSetAttribute(hmma_gemm<1>, cudaFuncAttributeMaxDynamicSharedMemorySize, SMEM_DYN);

    split_x_kernel<<<(MTOT * DIM / 4) / 256, 256>>>(x);
    prep_w_kernel<<<dim3(DIM / 32, DIM / 32, 4), 256>>>(Wq, Wk, Wv, Wo);

    // QKV: fused 3 GEMMs with scatter epilogue
    hmma_gemm<1><<<dim3(DIM / 128, MTOT / 128, 3), 256, SMEM_DYN>>>(nullptr);

    attn_kernel<<<dim3(SEQ / 64, HEADS, BB), 256>>>();

    // out = O @ Wo
    hmma_gemm<0><<<dim3(DIM / 128, MTOT / 128, 1), 256, SMEM_DYN>>>(out);
}

// round 4
// speedup vs baseline: 3.1895x; 2.3524x over previous
#include <cuda_runtime.h>
#include <cuda_bf16.h>
#include <math.h>
#include <stdint.h>

#define BB    2
#define SEQ   2048
#define DIM   1024
#define HEADS 16
#define DH    64
#define MTOT  (BB * SEQ)   // 4096

// ---------------------------------------------------------------------------
// Scratch (device globals: allocation-free, harness-safe)
// ---------------------------------------------------------------------------
__device__ __align__(16) __nv_bfloat16 gX0[(size_t)MTOT * DIM];
__device__ __align__(16) __nv_bfloat16 gX1[(size_t)MTOT * DIM];
__device__ __align__(16) __nv_bfloat16 gW0[(size_t)4 * DIM * DIM];
__device__ __align__(16) __nv_bfloat16 gW1[(size_t)4 * DIM * DIM];
__device__ __align__(16) __nv_bfloat16 gQ0[(size_t)MTOT * DIM];  // [B,H,S,DH]
__device__ __align__(16) __nv_bfloat16 gQ1[(size_t)MTOT * DIM];
__device__ __align__(16) __nv_bfloat16 gK0[(size_t)MTOT * DIM];
__device__ __align__(16) __nv_bfloat16 gK1[(size_t)MTOT * DIM];
__device__ __align__(16) __nv_bfloat16 gV0[(size_t)MTOT * DIM];
__device__ __align__(16) __nv_bfloat16 gV1[(size_t)MTOT * DIM];
__device__ __align__(16) __nv_bfloat16 gO0[(size_t)MTOT * DIM];  // [m][k]
__device__ __align__(16) __nv_bfloat16 gO1[(size_t)MTOT * DIM];

// ---------------------------------------------------------------------------
// PTX helpers (sm_80+ baseline)
// ---------------------------------------------------------------------------
__device__ __forceinline__ uint32_t smem_u32(const void* p) {
    uint32_t a;
    asm("{ .reg .u64 t; cvta.to.shared.u64 t, %1; cvt.u32.u64 %0, t; }"
        : "=r"(a) : "l"(p));
    return a;
}
__device__ __forceinline__ void ldm_x4(uint32_t* r, uint32_t addr) {
    asm volatile("ldmatrix.sync.aligned.m8n8.x4.shared.b16 {%0,%1,%2,%3}, [%4];"
                 : "=r"(r[0]), "=r"(r[1]), "=r"(r[2]), "=r"(r[3]) : "r"(addr));
}
__device__ __forceinline__ void ldm_x4_t(uint32_t* r, uint32_t addr) {
    asm volatile("ldmatrix.sync.aligned.m8n8.x4.trans.shared.b16 {%0,%1,%2,%3}, [%4];"
                 : "=r"(r[0]), "=r"(r[1]), "=r"(r[2]), "=r"(r[3]) : "r"(addr));
}
__device__ __forceinline__ void mma16816(float* d, const uint32_t* a,
                                         const uint32_t* b) {
    asm volatile(
        "mma.sync.aligned.m16n8k16.row.col.f32.bf16.bf16.f32 "
        "{%0,%1,%2,%3}, {%4,%5,%6,%7}, {%8,%9}, {%0,%1,%2,%3};"
        : "+f"(d[0]), "+f"(d[1]), "+f"(d[2]), "+f"(d[3])
        : "r"(a[0]), "r"(a[1]), "r"(a[2]), "r"(a[3]), "r"(b[0]), "r"(b[1]));
}
__device__ __forceinline__ void cp16(uint32_t s, const void* g) {
    asm volatile("cp.async.cg.shared.global [%0], [%1], 16;" :: "r"(s), "l"(g));
}
#define CP_COMMIT() asm volatile("cp.async.commit_group;" ::: "memory")
#define CP_WAIT(n)  asm volatile("cp.async.wait_group %0;" :: "n"(n) : "memory")

__device__ __forceinline__ uint32_t packbf2(float a, float b) {
    __nv_bfloat162 t = __floats2bfloat162_rn(a, b);
    return *(uint32_t*)&t;
}
__device__ __forceinline__ void split2(float a, float b, uint32_t& hi, uint32_t& lo) {
    const __nv_bfloat16 ha = __float2bfloat16_rn(a);
    const __nv_bfloat16 hb = __float2bfloat16_rn(b);
    __nv_bfloat162 t; t.x = ha; t.y = hb;
    hi = *(uint32_t*)&t;
    lo = packbf2(a - __bfloat162float(ha), b - __bfloat162float(hb));
}

// ---------------------------------------------------------------------------
// HMMA bf16x3 GEMM (unchanged math; MODE 1 epilogue emits split bf16 QKV)
// ---------------------------------------------------------------------------
#define AST   80
#define ARR   10240
#define STG   40960
#define SMEM_DYN (2 * STG)
#define NSLAB (DIM / 32)

template <int MODE>
__global__ __launch_bounds__(256) void hmma_gemm(float* __restrict__ outp) {
    extern __shared__ char smem_raw[];
    const uint32_t sbase = smem_u32(smem_raw);
    const int tid  = threadIdx.x;
    const int lane = tid & 31;
    const int wid  = tid >> 5;
    const int z    = blockIdx.z;
    const int m0   = blockIdx.y * 128;
    const int n0   = blockIdx.x * 128;

    const __nv_bfloat16* A0g = (MODE == 1) ? gX0 : gO0;
    const __nv_bfloat16* A1g = (MODE == 1) ? gX1 : gO1;
    const size_t woff = (MODE == 1) ? (size_t)z * DIM * DIM : (size_t)3 * DIM * DIM;
    const __nv_bfloat16* B0g = gW0 + woff;
    const __nv_bfloat16* B1g = gW1 + woff;

    const int ldr = tid >> 2;
    const int ldc = tid & 3;

    float acc[2][8][4];
#pragma unroll
    for (int mi = 0; mi < 2; mi++)
#pragma unroll
        for (int ni = 0; ni < 8; ni++)
#pragma unroll
            for (int u = 0; u < 4; u++) acc[mi][ni][u] = 0.0f;

    const int wm = (wid & 3) * 32;
    const int wn = (wid >> 2) * 64;
    const int lrow  = lane & 15;
    const int lcolb = (lane >> 4) * 16;

#define ISSUE_SLAB(s) do {                                                    \
        const int _st = (s) & 1;                                              \
        const int _k0 = (s) * 32;                                             \
        _Pragma("unroll")                                                     \
        for (int t = 0; t < 2; t++) {                                         \
            const int r = ldr + t * 64;                                       \
            const size_t ga = (size_t)(m0 + r) * DIM + _k0 + ldc * 8;         \
            const uint32_t sa = sbase + _st * STG + r * AST + ldc * 16;       \
            cp16(sa, A0g + ga);                                               \
            cp16(sa + ARR, A1g + ga);                                         \
            const size_t gb = (size_t)(n0 + r) * DIM + _k0 + ldc * 8;         \
            const uint32_t sb = sbase + _st * STG + 2 * ARR + r * AST + ldc * 16; \
            cp16(sb, B0g + gb);                                               \
            cp16(sb + ARR, B1g + gb);                                         \
        }                                                                     \
        CP_COMMIT();                                                          \
    } while (0)

    ISSUE_SLAB(0);
    for (int s = 0; s < NSLAB; s++) {
        if (s + 1 < NSLAB) { ISSUE_SLAB(s + 1); CP_WAIT(1); }
        else               { CP_WAIT(0); }
        __syncthreads();

        const uint32_t stoff = (uint32_t)(s & 1) * STG;
#pragma unroll
        for (int j = 0; j < 2; j++) {
            const uint32_t kb = j * 32 + lcolb;
            uint32_t a0f[2][4], a1f[2][4];
#pragma unroll
            for (int mi = 0; mi < 2; mi++) {
                const uint32_t ad = sbase + stoff + (wm + mi * 16 + lrow) * AST + kb;
                ldm_x4(a0f[mi], ad);
                ldm_x4(a1f[mi], ad + ARR);
            }
            uint32_t b0f[8][2], b1f[8][2];
#pragma unroll
            for (int nt = 0; nt < 4; nt++) {
                const uint32_t bd = sbase + stoff + 2 * ARR + (wn + nt * 16 + lrow) * AST + kb;
                uint32_t r4[4];
                ldm_x4(r4, bd);
                b0f[nt * 2][0]     = r4[0]; b0f[nt * 2][1]     = r4[2];
                b0f[nt * 2 + 1][0] = r4[1]; b0f[nt * 2 + 1][1] = r4[3];
                ldm_x4(r4, bd + ARR);
                b1f[nt * 2][0]     = r4[0]; b1f[nt * 2][1]     = r4[2];
                b1f[nt * 2 + 1][0] = r4[1]; b1f[nt * 2 + 1][1] = r4[3];
            }
#pragma unroll
            for (int mi = 0; mi < 2; mi++)
#pragma unroll
                for (int ni = 0; ni < 8; ni++) {
                    mma16816(acc[mi][ni], a0f[mi], b0f[ni]);
                    mma16816(acc[mi][ni], a0f[mi], b1f[ni]);
                    mma16816(acc[mi][ni], a1f[mi], b0f[ni]);
                }
        }
        __syncthreads();
    }

#pragma unroll
    for (int mi = 0; mi < 2; mi++)
#pragma unroll
        for (int ni = 0; ni < 8; ni++) {
            const int cc = n0 + wn + ni * 8 + (lane & 3) * 2;
#pragma unroll
            for (int h2 = 0; h2 < 2; h2++) {
                const int m = m0 + wm + mi * 16 + (lane >> 2) + h2 * 8;
                const float ox = acc[mi][ni][h2 * 2];
                const float oy = acc[mi][ni][h2 * 2 + 1];
                if (MODE == 0) {
                    *(float2*)(outp + (size_t)m * DIM + cc) = make_float2(ox, oy);
                } else {
                    const int b = m >> 11, sq = m & (SEQ - 1);
                    const int h = cc >> 6, d0 = cc & 63;
                    __nv_bfloat16* G0 = (z == 0) ? gQ0 : (z == 1) ? gK0 : gV0;
                    __nv_bfloat16* G1 = (z == 0) ? gQ1 : (z == 1) ? gK1 : gV1;
                    const size_t idx = ((size_t)(b * HEADS + h) * SEQ + sq) * DH + d0;
                    uint32_t hi, lo;
                    split2(ox, oy, hi, lo);
                    *(uint32_t*)(G0 + idx) = hi;
                    *(uint32_t*)(G1 + idx) = lo;
                }
            }
        }
}

// ---------------------------------------------------------------------------
// Prep kernels
// ---------------------------------------------------------------------------
__global__ __launch_bounds__(256) void split_x_kernel(const float* __restrict__ x) {
    const int i = blockIdx.x * 256 + threadIdx.x;
    const float4 v = ((const float4*)x)[i];
    union { __nv_bfloat16 h[4]; uint2 u; } H, L;
    const float f[4] = {v.x, v.y, v.z, v.w};
#pragma unroll
    for (int j = 0; j < 4; j++) {
        H.h[j] = __float2bfloat16_rn(f[j]);
        L.h[j] = __float2bfloat16_rn(f[j] - __bfloat162float(H.h[j]));
    }
    *(uint2*)(gX0 + (size_t)i * 4) = H.u;
    *(uint2*)(gX1 + (size_t)i * 4) = L.u;
}

__global__ __launch_bounds__(256) void prep_w_kernel(const float* __restrict__ Wq,
                                                     const float* __restrict__ Wk,
                                                     const float* __restrict__ Wv,
                                                     const float* __restrict__ Wo) {
    __shared__ float tile[32][33];
    const int z = blockIdx.z;
    const float* W = (z == 0) ? Wq : (z == 1) ? Wk : (z == 2) ? Wv : Wo;
    __nv_bfloat16* T0 = gW0 + (size_t)z * DIM * DIM;
    __nv_bfloat16* T1 = gW1 + (size_t)z * DIM * DIM;
    const int n0 = blockIdx.x * 32, k0 = blockIdx.y * 32;
    const int tx = threadIdx.x & 31, ty = threadIdx.x >> 5;
#pragma unroll
    for (int i = 0; i < 4; i++)
        tile[ty + 8 * i][tx] = W[(size_t)(k0 + ty + 8 * i) * DIM + n0 + tx];
    __syncthreads();
#pragma unroll
    for (int i = 0; i < 4; i++) {
        const int n = n0 + ty + 8 * i;
        const float v = tile[tx][ty + 8 * i];
        const __nv_bfloat16 hi = __float2bfloat16_rn(v);
        T0[(size_t)n * DIM + k0 + tx] = hi;
        T1[(size_t)n * DIM + k0 + tx] = __float2bfloat16_rn(v - __bfloat162float(hi));
    }
}

// ---------------------------------------------------------------------------
// Flash attention on mma.sync, bf16x3 splits, causal.
// q-tile 128 (8 warps x 16 rows), kv-tile 64, 2-stage cp.async.
// Smem: [Q0 18432][Q1 18432][stage0: K0,K1,V0,V1 @9216][stage1 ...]
// ---------------------------------------------------------------------------
#define ASTR       144
#define AQ_BYTES   (128 * ASTR)      // 18432
#define AKV_BYTES  (64 * ASTR)       // 9216
#define ASTAGE     (4 * AKV_BYTES)   // 36864
#define ATTN_SMEM  (2 * AQ_BYTES + 2 * ASTAGE)   // 110592

__global__ __launch_bounds__(256) void attn_mma() {
    extern __shared__ char smem_raw[];
    const uint32_t sb = smem_u32(smem_raw);
    const int tid  = threadIdx.x;
    const int lane = tid & 31;
    const int wid  = tid >> 5;
    const int qt   = (int)gridDim.x - 1 - (int)blockIdx.x;   // heavy tiles first
    const int h    = blockIdx.y;
    const int b    = blockIdx.z;
    const int q0   = qt * 128;
    const size_t hoff = (size_t)(b * HEADS + h) * SEQ * DH;
    const __nv_bfloat16* Q0g = gQ0 + hoff;
    const __nv_bfloat16* Q1g = gQ1 + hoff;
    const __nv_bfloat16* K0g = gK0 + hoff;
    const __nv_bfloat16* K1g = gK1 + hoff;
    const __nv_bfloat16* V0g = gV0 + hoff;
    const __nv_bfloat16* V1g = gV1 + hoff;

    const uint32_t sStage = sb + 2 * AQ_BYTES;

    // Q loads: 2 arrays x 128 rows x 8 chunks
#pragma unroll
    for (int t = 0; t < 8; t++) {
        const int v = tid + t * 256;
        const int arr = v >> 10;
        const int rem = v & 1023;
        const int r = rem >> 3, c = rem & 7;
        const __nv_bfloat16* src = (arr ? Q1g : Q0g) + (size_t)(q0 + r) * DH + c * 8;
        cp16(sb + arr * AQ_BYTES + r * ASTR + c * 16, src);
    }

#define ISSUE_KV(kt) do {                                                      \
        const int _k0 = (kt) * 64;                                             \
        const uint32_t _dst = sStage + (uint32_t)((kt) & 1) * ASTAGE;           \
        _Pragma("unroll")                                                       \
        for (int t = 0; t < 8; t++) {                                           \
            const int v = tid + t * 256;                                        \
            const int arr = v >> 9;                                             \
            const int rem = v & 511;                                            \
            const int r = rem >> 3, c = rem & 7;                                \
            const __nv_bfloat16* src =                                          \
                ((arr == 0) ? K0g : (arr == 1) ? K1g : (arr == 2) ? V0g : V1g)  \
                + (size_t)(_k0 + r) * DH + c * 8;                               \
            cp16(_dst + arr * AKV_BYTES + r * ASTR + c * 16, src);              \
        }                                                                       \
        CP_COMMIT();                                                            \
    } while (0)

    ISSUE_KV(0);   // shares the first commit group with Q

    const int wm = wid * 16;
    float acc[8][4];
#pragma unroll
    for (int j = 0; j < 8; j++)
#pragma unroll
        for (int e = 0; e < 4; e++) acc[j][e] = 0.0f;
    float mi0 = -INFINITY, mi1 = -INFINITY, li0 = 0.0f, li1 = 0.0f;
    uint32_t qf0[4][4], qf1[4][4];

    const int nkt = 2 * (qt + 1);
    for (int kt = 0; kt < nkt; kt++) {
        if (kt + 1 < nkt) { ISSUE_KV(kt + 1); CP_WAIT(1); }
        else              { CP_WAIT(0); }
        __syncthreads();

        if (kt == 0) {
#pragma unroll
            for (int ks = 0; ks < 4; ks++) {
                const uint32_t ad =
                    sb + (wm + (lane & 15)) * ASTR + ks * 32 + (lane >> 4) * 16;
                ldm_x4(qf0[ks], ad);
                ldm_x4(qf1[ks], ad + AQ_BYTES);
            }
        }

        const uint32_t stg = sStage + (uint32_t)(kt & 1) * ASTAGE;
        const int k0 = kt * 64;
        const bool skip = (k0 > q0 + wm + 15);
        if (!skip) {
            // ---- scores S = Q K^T ----
            float s[8][4];
#pragma unroll
            for (int j = 0; j < 8; j++)
#pragma unroll
                for (int e = 0; e < 4; e++) s[j][e] = 0.0f;
#pragma unroll
            for (int ks = 0; ks < 4; ks++) {
#pragma unroll
                for (int nt = 0; nt < 4; nt++) {
                    const uint32_t ad =
                        stg + (nt * 16 + (lane & 15)) * ASTR + ks * 32 + (lane >> 4) * 16;
                    uint32_t r4[4], r5[4];
                    ldm_x4(r4, ad);                 // K hi
                    ldm_x4(r5, ad + AKV_BYTES);     // K lo
                    uint32_t b00[2] = {r4[0], r4[2]}, b01[2] = {r4[1], r4[3]};
                    uint32_t b10[2] = {r5[0], r5[2]}, b11[2] = {r5[1], r5[3]};
                    mma16816(s[nt * 2],     qf0[ks], b00);
                    mma16816(s[nt * 2],     qf1[ks], b00);
                    mma16816(s[nt * 2],     qf0[ks], b10);
                    mma16816(s[nt * 2 + 1], qf0[ks], b01);
                    mma16816(s[nt * 2 + 1], qf1[ks], b01);
                    mma16816(s[nt * 2 + 1], qf0[ks], b11);
                }
            }

            // ---- mask + scale ----
            const int row0 = q0 + wm + (lane >> 2);
            const int row1 = row0 + 8;
            const bool needmask = (k0 + 63 > q0 + wm);
            if (needmask) {
#pragma unroll
                for (int j = 0; j < 8; j++) {
                    const int cbase = k0 + j * 8 + (lane & 3) * 2;
                    s[j][0] = (cbase     <= row0) ? s[j][0] * 0.125f : -INFINITY;
                    s[j][1] = (cbase + 1 <= row0) ? s[j][1] * 0.125f : -INFINITY;
                    s[j][2] = (cbase     <= row1) ? s[j][2] * 0.125f : -INFINITY;
                    s[j][3] = (cbase + 1 <= row1) ? s[j][3] * 0.125f : -INFINITY;
                }
            } else {
#pragma unroll
                for (int j = 0; j < 8; j++)
#pragma unroll
                    for (int e = 0; e < 4; e++) s[j][e] *= 0.125f;
            }

            // ---- online softmax ----
            float tm0 = -INFINITY, tm1 = -INFINITY;
#pragma unroll
            for (int j = 0; j < 8; j++) {
                tm0 = fmaxf(tm0, fmaxf(s[j][0], s[j][1]));
                tm1 = fmaxf(tm1, fmaxf(s[j][2], s[j][3]));
            }
            tm0 = fmaxf(tm0, __shfl_xor_sync(0xffffffffu, tm0, 1));
            tm0 = fmaxf(tm0, __shfl_xor_sync(0xffffffffu, tm0, 2));
            tm1 = fmaxf(tm1, __shfl_xor_sync(0xffffffffu, tm1, 1));
            tm1 = fmaxf(tm1, __shfl_xor_sync(0xffffffffu, tm1, 2));
            const float mn0 = fmaxf(mi0, tm0);
            const float mn1 = fmaxf(mi1, tm1);
            const float c0 = __expf(mi0 - mn0);
            const float c1 = __expf(mi1 - mn1);
            float ls0 = 0.0f, ls1 = 0.0f;
#pragma unroll
            for (int j = 0; j < 8; j++) {
                s[j][0] = __expf(s[j][0] - mn0);
                s[j][1] = __expf(s[j][1] - mn0);
                s[j][2] = __expf(s[j][2] - mn1);
                s[j][3] = __expf(s[j][3] - mn1);
                ls0 += s[j][0] + s[j][1];
                ls1 += s[j][2] + s[j][3];
            }
            ls0 += __shfl_xor_sync(0xffffffffu, ls0, 1);
            ls0 += __shfl_xor_sync(0xffffffffu, ls0, 2);
            ls1 += __shfl_xor_sync(0xffffffffu, ls1, 1);
            ls1 += __shfl_xor_sync(0xffffffffu, ls1, 2);
            li0 = li0 * c0 + ls0;
            li1 = li1 * c1 + ls1;
            mi0 = mn0; mi1 = mn1;
#pragma unroll
            for (int j = 0; j < 8; j++) {
                acc[j][0] *= c0; acc[j][1] *= c0;
                acc[j][2] *= c1; acc[j][3] *= c1;
            }

            // ---- PV: acc += P V ----
#pragma unroll
            for (int ks = 0; ks < 4; ks++) {
                uint32_t A0[4], A1[4];
                split2(s[2 * ks][0],     s[2 * ks][1],     A0[0], A1[0]);
                split2(s[2 * ks][2],     s[2 * ks][3],     A0[1], A1[1]);
                split2(s[2 * ks + 1][0], s[2 * ks + 1][1], A0[2], A1[2]);
                split2(s[2 * ks + 1][2], s[2 * ks + 1][3], A0[3], A1[3]);
#pragma unroll
                for (int dvt = 0; dvt < 4; dvt++) {
                    const uint32_t ad = stg + 2 * AKV_BYTES +
                        (ks * 16 + (lane & 15)) * ASTR +
                        dvt * 32 + (lane >> 4) * 16;
                    uint32_t r4[4], r5[4];
                    ldm_x4_t(r4, ad);               // V hi (transposed)
                    ldm_x4_t(r5, ad + AKV_BYTES);   // V lo
                    uint32_t vb0a[2] = {r4[0], r4[1]}, vb0b[2] = {r4[2], r4[3]};
                    uint32_t vb1a[2] = {r5[0], r5[1]}, vb1b[2] = {r5[2], r5[3]};
                    mma16816(acc[2 * dvt],     A0, vb0a);
                    mma16816(acc[2 * dvt],     A0, vb1a);
                    mma16816(acc[2 * dvt],     A1, vb0a);
                    mma16816(acc[2 * dvt + 1], A0, vb0b);
                    mma16816(acc[2 * dvt + 1], A0, vb1b);
                    mma16816(acc[2 * dvt + 1], A1, vb0b);
                }
            }
        }
        __syncthreads();
    }

    // ---- epilogue: O rows -> split bf16 gO0/gO1 ----
    const float inv0 = 1.0f / li0;
    const float inv1 = 1.0f / li1;
    const int row0 = q0 + wm + (lane >> 2);
    const int row1 = row0 + 8;
    const size_t ob0 = ((size_t)b * SEQ + row0) * DIM + h * DH;
    const size_t ob1 = ((size_t)b * SEQ + row1) * DIM + h * DH;
#pragma unroll
    for (int j = 0; j < 8; j++) {
        const int dv = j * 8 + (lane & 3) * 2;
        uint32_t hi, lo;
        split2(acc[j][0] * inv0, acc[j][1] * inv0, hi, lo);
        *(uint32_t*)(gO0 + ob0 + dv) = hi;
        *(uint32_t*)(gO1 + ob0 + dv) = lo;
        split2(acc[j][2] * inv1, acc[j][3] * inv1, hi, lo);
        *(uint32_t*)(gO0 + ob1 + dv) = hi;
        *(uint32_t*)(gO1 + ob1 + dv) = lo;
    }
}

// ---------------------------------------------------------------------------
// kernel_launch
// ---------------------------------------------------------------------------
extern "C" void kernel_launch(void* const* d_in, const int* in_sizes, int n_in,
                              void* d_out, int out_size) {
    const float* x  = (const float*)d_in[0];
    // d_in[1] = causal mask (structure known, unused)
    const float* Wq = (const float*)d_in[2];
    const float* Wk = (const float*)d_in[3];
    const float* Wv = (const float*)d_in[4];
    const float* Wo = (const float*)d_in[5];
    float* out = (float*)d_out;

    cudaFuncSetAttribute(hmma_gemm<0>, cudaFuncAttributeMaxDynamicSharedMemorySize, SMEM_DYN);
    cudaFuncSetAttribute(hmma_gemm<1>, cudaFuncAttributeMaxDynamicSharedMemorySize, SMEM_DYN);
    cudaFuncSetAttribute(attn_mma, cudaFuncAttributeMaxDynamicSharedMemorySize, ATTN_SMEM);

    split_x_kernel<<<(MTOT * DIM / 4) / 256, 256>>>(x);
    prep_w_kernel<<<dim3(DIM / 32, DIM / 32, 4), 256>>>(Wq, Wk, Wv, Wo);

    hmma_gemm<1><<<dim3(DIM / 128, MTOT / 128, 3), 256, SMEM_DYN>>>(nullptr);

    attn_mma<<<dim3(SEQ / 128, HEADS, BB), 256, ATTN_SMEM>>>();

    hmma_gemm<0><<<dim3(DIM / 128, MTOT / 128, 1), 256, SMEM_DYN>>>(out);
}

// round 6
// speedup vs baseline: 3.6593x; 1.1473x over previous
#include <cuda_runtime.h>
#include <cuda_bf16.h>
#include <cuda_fp16.h>
#include <math.h>
#include <stdint.h>

#define BB    2
#define SEQ   2048
#define DIM   1024
#define HEADS 16
#define DH    64
#define MTOT  (BB * SEQ)   // 4096

// ---------------------------------------------------------------------------
// Scratch (device globals: allocation-free, harness-safe)
// ---------------------------------------------------------------------------
__device__ __align__(16) __nv_bfloat16 gX0[(size_t)MTOT * DIM];
__device__ __align__(16) __nv_bfloat16 gX1[(size_t)MTOT * DIM];
__device__ __align__(16) __nv_bfloat16 gW0[(size_t)4 * DIM * DIM];
__device__ __align__(16) __nv_bfloat16 gW1[(size_t)4 * DIM * DIM];
__device__ __align__(16) __nv_bfloat16 gQ0[(size_t)MTOT * DIM];  // [B,H,S,DH]
__device__ __align__(16) __nv_bfloat16 gQ1[(size_t)MTOT * DIM];
__device__ __align__(16) __nv_bfloat16 gK0[(size_t)MTOT * DIM];
__device__ __align__(16) __nv_bfloat16 gK1[(size_t)MTOT * DIM];
__device__ __align__(16) __half        gVh[(size_t)MTOT * DIM];  // V as fp16
__device__ __align__(16) __nv_bfloat16 gO0[(size_t)MTOT * DIM];  // [m][k]
__device__ __align__(16) __nv_bfloat16 gO1[(size_t)MTOT * DIM];

// ---------------------------------------------------------------------------
// PTX helpers (sm_80+ baseline)
// ---------------------------------------------------------------------------
__device__ __forceinline__ uint32_t smem_u32(const void* p) {
    uint32_t a;
    asm("{ .reg .u64 t; cvta.to.shared.u64 t, %1; cvt.u32.u64 %0, t; }"
        : "=r"(a) : "l"(p));
    return a;
}
__device__ __forceinline__ void ldm_x4(uint32_t* r, uint32_t addr) {
    asm volatile("ldmatrix.sync.aligned.m8n8.x4.shared.b16 {%0,%1,%2,%3}, [%4];"
                 : "=r"(r[0]), "=r"(r[1]), "=r"(r[2]), "=r"(r[3]) : "r"(addr));
}
__device__ __forceinline__ void ldm_x4_t(uint32_t* r, uint32_t addr) {
    asm volatile("ldmatrix.sync.aligned.m8n8.x4.trans.shared.b16 {%0,%1,%2,%3}, [%4];"
                 : "=r"(r[0]), "=r"(r[1]), "=r"(r[2]), "=r"(r[3]) : "r"(addr));
}
__device__ __forceinline__ void mma16816(float* d, const uint32_t* a,
                                         const uint32_t* b) {
    asm volatile(
        "mma.sync.aligned.m16n8k16.row.col.f32.bf16.bf16.f32 "
        "{%0,%1,%2,%3}, {%4,%5,%6,%7}, {%8,%9}, {%0,%1,%2,%3};"
        : "+f"(d[0]), "+f"(d[1]), "+f"(d[2]), "+f"(d[3])
        : "r"(a[0]), "r"(a[1]), "r"(a[2]), "r"(a[3]), "r"(b[0]), "r"(b[1]));
}
__device__ __forceinline__ void mma16816h(float* d, const uint32_t* a,
                                          const uint32_t* b) {
    asm volatile(
        "mma.sync.aligned.m16n8k16.row.col.f32.f16.f16.f32 "
        "{%0,%1,%2,%3}, {%4,%5,%6,%7}, {%8,%9}, {%0,%1,%2,%3};"
        : "+f"(d[0]), "+f"(d[1]), "+f"(d[2]), "+f"(d[3])
        : "r"(a[0]), "r"(a[1]), "r"(a[2]), "r"(a[3]), "r"(b[0]), "r"(b[1]));
}
__device__ __forceinline__ void cp16(uint32_t s, const void* g) {
    asm volatile("cp.async.cg.shared.global [%0], [%1], 16;" :: "r"(s), "l"(g));
}
#define CP_COMMIT() asm volatile("cp.async.commit_group;" ::: "memory")
#define CP_WAIT(n)  asm volatile("cp.async.wait_group %0;" :: "n"(n) : "memory")

__device__ __forceinline__ uint32_t packbf2(float a, float b) {
    __nv_bfloat162 t = __floats2bfloat162_rn(a, b);
    return *(uint32_t*)&t;
}
__device__ __forceinline__ uint32_t packh2(float a, float b) {
    __half2 t = __floats2half2_rn(a, b);
    return *(uint32_t*)&t;
}
__device__ __forceinline__ void split2(float a, float b, uint32_t& hi, uint32_t& lo) {
    const __nv_bfloat16 ha = __float2bfloat16_rn(a);
    const __nv_bfloat16 hb = __float2bfloat16_rn(b);
    __nv_bfloat162 t; t.x = ha; t.y = hb;
    hi = *(uint32_t*)&t;
    lo = packbf2(a - __bfloat162float(ha), b - __bfloat162float(hb));
}

// ---------------------------------------------------------------------------
// HMMA bf16x3 GEMM; MODE 1 epilogue emits split bf16 Q/K, fp16 V
// ---------------------------------------------------------------------------
#define AST   80
#define ARR   10240
#define STG   40960
#define SMEM_DYN (2 * STG)
#define NSLAB (DIM / 32)

template <int MODE>
__global__ __launch_bounds__(256) void hmma_gemm(float* __restrict__ outp) {
    extern __shared__ char smem_raw[];
    const uint32_t sbase = smem_u32(smem_raw);
    const int tid  = threadIdx.x;
    const int lane = tid & 31;
    const int wid  = tid >> 5;
    const int z    = blockIdx.z;
    const int m0   = blockIdx.y * 128;
    const int n0   = blockIdx.x * 128;

    const __nv_bfloat16* A0g = (MODE == 1) ? gX0 : gO0;
    const __nv_bfloat16* A1g = (MODE == 1) ? gX1 : gO1;
    const size_t woff = (MODE == 1) ? (size_t)z * DIM * DIM : (size_t)3 * DIM * DIM;
    const __nv_bfloat16* B0g = gW0 + woff;
    const __nv_bfloat16* B1g = gW1 + woff;

    const int ldr = tid >> 2;
    const int ldc = tid & 3;

    float acc[2][8][4];
#pragma unroll
    for (int mi = 0; mi < 2; mi++)
#pragma unroll
        for (int ni = 0; ni < 8; ni++)
#pragma unroll
            for (int u = 0; u < 4; u++) acc[mi][ni][u] = 0.0f;

    const int wm = (wid & 3) * 32;
    const int wn = (wid >> 2) * 64;
    const int lrow  = lane & 15;
    const int lcolb = (lane >> 4) * 16;

#define ISSUE_SLAB(s) do {                                                    \
        const int _st = (s) & 1;                                              \
        const int _k0 = (s) * 32;                                             \
        _Pragma("unroll")                                                     \
        for (int t = 0; t < 2; t++) {                                         \
            const int r = ldr + t * 64;                                       \
            const size_t ga = (size_t)(m0 + r) * DIM + _k0 + ldc * 8;         \
            const uint32_t sa = sbase + _st * STG + r * AST + ldc * 16;       \
            cp16(sa, A0g + ga);                                               \
            cp16(sa + ARR, A1g + ga);                                         \
            const size_t gb = (size_t)(n0 + r) * DIM + _k0 + ldc * 8;         \
            const uint32_t sb = sbase + _st * STG + 2 * ARR + r * AST + ldc * 16; \
            cp16(sb, B0g + gb);                                               \
            cp16(sb + ARR, B1g + gb);                                         \
        }                                                                     \
        CP_COMMIT();                                                          \
    } while (0)

    ISSUE_SLAB(0);
    for (int s = 0; s < NSLAB; s++) {
        if (s + 1 < NSLAB) { ISSUE_SLAB(s + 1); CP_WAIT(1); }
        else               { CP_WAIT(0); }
        __syncthreads();

        const uint32_t stoff = (uint32_t)(s & 1) * STG;
#pragma unroll
        for (int j = 0; j < 2; j++) {
            const uint32_t kb = j * 32 + lcolb;
            uint32_t a0f[2][4], a1f[2][4];
#pragma unroll
            for (int mi = 0; mi < 2; mi++) {
                const uint32_t ad = sbase + stoff + (wm + mi * 16 + lrow) * AST + kb;
                ldm_x4(a0f[mi], ad);
                ldm_x4(a1f[mi], ad + ARR);
            }
            uint32_t b0f[8][2], b1f[8][2];
#pragma unroll
            for (int nt = 0; nt < 4; nt++) {
                const uint32_t bd = sbase + stoff + 2 * ARR + (wn + nt * 16 + lrow) * AST + kb;
                uint32_t r4[4];
                ldm_x4(r4, bd);
                b0f[nt * 2][0]     = r4[0]; b0f[nt * 2][1]     = r4[2];
                b0f[nt * 2 + 1][0] = r4[1]; b0f[nt * 2 + 1][1] = r4[3];
                ldm_x4(r4, bd + ARR);
                b1f[nt * 2][0]     = r4[0]; b1f[nt * 2][1]     = r4[2];
                b1f[nt * 2 + 1][0] = r4[1]; b1f[nt * 2 + 1][1] = r4[3];
            }
#pragma unroll
            for (int mi = 0; mi < 2; mi++)
#pragma unroll
                for (int ni = 0; ni < 8; ni++) {
                    mma16816(acc[mi][ni], a0f[mi], b0f[ni]);
                    mma16816(acc[mi][ni], a0f[mi], b1f[ni]);
                    mma16816(acc[mi][ni], a1f[mi], b0f[ni]);
                }
        }
        __syncthreads();
    }

#pragma unroll
    for (int mi = 0; mi < 2; mi++)
#pragma unroll
        for (int ni = 0; ni < 8; ni++) {
            const int cc = n0 + wn + ni * 8 + (lane & 3) * 2;
#pragma unroll
            for (int h2 = 0; h2 < 2; h2++) {
                const int m = m0 + wm + mi * 16 + (lane >> 2) + h2 * 8;
                const float ox = acc[mi][ni][h2 * 2];
                const float oy = acc[mi][ni][h2 * 2 + 1];
                if (MODE == 0) {
                    *(float2*)(outp + (size_t)m * DIM + cc) = make_float2(ox, oy);
                } else {
                    const int b = m >> 11, sq = m & (SEQ - 1);
                    const int h = cc >> 6, d0 = cc & 63;
                    const size_t idx = ((size_t)(b * HEADS + h) * SEQ + sq) * DH + d0;
                    if (z == 2) {
                        *(uint32_t*)(gVh + idx) = packh2(ox, oy);
                    } else {
                        __nv_bfloat16* G0 = (z == 0) ? gQ0 : gK0;
                        __nv_bfloat16* G1 = (z == 0) ? gQ1 : gK1;
                        uint32_t hi, lo;
                        split2(ox, oy, hi, lo);
                        *(uint32_t*)(G0 + idx) = hi;
                        *(uint32_t*)(G1 + idx) = lo;
                    }
                }
            }
        }
}

// ---------------------------------------------------------------------------
// Prep kernels
// ---------------------------------------------------------------------------
__global__ __launch_bounds__(256) void split_x_kernel(const float* __restrict__ x) {
    const int i = blockIdx.x * 256 + threadIdx.x;
    const float4 v = ((const float4*)x)[i];
    union { __nv_bfloat16 h[4]; uint2 u; } H, L;
    const float f[4] = {v.x, v.y, v.z, v.w};
#pragma unroll
    for (int j = 0; j < 4; j++) {
        H.h[j] = __float2bfloat16_rn(f[j]);
        L.h[j] = __float2bfloat16_rn(f[j] - __bfloat162float(H.h[j]));
    }
    *(uint2*)(gX0 + (size_t)i * 4) = H.u;
    *(uint2*)(gX1 + (size_t)i * 4) = L.u;
}

__global__ __launch_bounds__(256) void prep_w_kernel(const float* __restrict__ Wq,
                                                     const float* __restrict__ Wk,
                                                     const float* __restrict__ Wv,
                                                     const float* __restrict__ Wo) {
    __shared__ float tile[32][33];
    const int z = blockIdx.z;
    const float* W = (z == 0) ? Wq : (z == 1) ? Wk : (z == 2) ? Wv : Wo;
    __nv_bfloat16* T0 = gW0 + (size_t)z * DIM * DIM;
    __nv_bfloat16* T1 = gW1 + (size_t)z * DIM * DIM;
    const int n0 = blockIdx.x * 32, k0 = blockIdx.y * 32;
    const int tx = threadIdx.x & 31, ty = threadIdx.x >> 5;
#pragma unroll
    for (int i = 0; i < 4; i++)
        tile[ty + 8 * i][tx] = W[(size_t)(k0 + ty + 8 * i) * DIM + n0 + tx];
    __syncthreads();
#pragma unroll
    for (int i = 0; i < 4; i++) {
        const int n = n0 + ty + 8 * i;
        const float v = tile[tx][ty + 8 * i];
        const __nv_bfloat16 hi = __float2bfloat16_rn(v);
        T0[(size_t)n * DIM + k0 + tx] = hi;
        T1[(size_t)n * DIM + k0 + tx] = __float2bfloat16_rn(v - __bfloat162float(hi));
    }
}

// ---------------------------------------------------------------------------
// Flash attention: QK^T bf16x3, PV single fp16. Causal.
// q-tile 128 (8 warps x 16 rows), kv-tile 64, 2-stage cp.async.
// Smem: [Q0 18432][Q1 18432][stage: K0,K1,Vh @9216 each][stage2 ...]
// ---------------------------------------------------------------------------
#define ASTR       144
#define AQ_BYTES   (128 * ASTR)      // 18432
#define AKV_BYTES  (64 * ASTR)       // 9216
#define ASTAGE     (3 * AKV_BYTES)   // 27648
#define ATTN_SMEM  (2 * AQ_BYTES + 2 * ASTAGE)   // 92160

__global__ __launch_bounds__(256) void attn_mma() {
    extern __shared__ char smem_raw[];
    const uint32_t sb = smem_u32(smem_raw);
    const int tid  = threadIdx.x;
    const int lane = tid & 31;
    const int wid  = tid >> 5;
    const int qt   = (int)gridDim.x - 1 - (int)blockIdx.x;   // heavy tiles first
    const int h    = blockIdx.y;
    const int b    = blockIdx.z;
    const int q0   = qt * 128;
    const size_t hoff = (size_t)(b * HEADS + h) * SEQ * DH;
    const __nv_bfloat16* Q0g = gQ0 + hoff;
    const __nv_bfloat16* Q1g = gQ1 + hoff;
    const __nv_bfloat16* K0g = gK0 + hoff;
    const __nv_bfloat16* K1g = gK1 + hoff;
    const __half*        Vg  = gVh + hoff;

    const uint32_t sStage = sb + 2 * AQ_BYTES;

    // Q loads: 2 arrays x 128 rows x 8 chunks
#pragma unroll
    for (int t = 0; t < 8; t++) {
        const int v = tid + t * 256;
        const int arr = v >> 10;
        const int rem = v & 1023;
        const int r = rem >> 3, c = rem & 7;
        const __nv_bfloat16* src = (arr ? Q1g : Q0g) + (size_t)(q0 + r) * DH + c * 8;
        cp16(sb + arr * AQ_BYTES + r * ASTR + c * 16, src);
    }

    // KV: K0,K1 (bf16) + V (fp16): 3 arrays x 64 rows x 8 chunks = 6 / thread
#define ISSUE_KV(kt) do {                                                      \
        const int _k0 = (kt) * 64;                                             \
        const uint32_t _dst = sStage + (uint32_t)((kt) & 1) * ASTAGE;           \
        _Pragma("unroll")                                                       \
        for (int t = 0; t < 6; t++) {                                           \
            const int v = tid + t * 256;                                        \
            const int arr = v >> 9;                                             \
            const int rem = v & 511;                                            \
            const int r = rem >> 3, c = rem & 7;                                \
            const void* src;                                                    \
            if (arr == 0)      src = K0g + (size_t)(_k0 + r) * DH + c * 8;      \
            else if (arr == 1) src = K1g + (size_t)(_k0 + r) * DH + c * 8;      \
            else               src = Vg  + (size_t)(_k0 + r) * DH + c * 8;      \
            cp16(_dst + arr * AKV_BYTES + r * ASTR + c * 16, src);              \
        }                                                                       \
        CP_COMMIT();                                                            \
    } while (0)

    ISSUE_KV(0);   // shares the first commit group with Q

    const int wm = wid * 16;
    float acc[8][4];
#pragma unroll
    for (int j = 0; j < 8; j++)
#pragma unroll
        for (int e = 0; e < 4; e++) acc[j][e] = 0.0f;
    float mi0 = -INFINITY, mi1 = -INFINITY, li0 = 0.0f, li1 = 0.0f;
    uint32_t qf0[4][4], qf1[4][4];

    const int nkt = 2 * (qt + 1);
    for (int kt = 0; kt < nkt; kt++) {
        if (kt + 1 < nkt) { ISSUE_KV(kt + 1); CP_WAIT(1); }
        else              { CP_WAIT(0); }
        __syncthreads();

        if (kt == 0) {
#pragma unroll
            for (int ks = 0; ks < 4; ks++) {
                const uint32_t ad =
                    sb + (wm + (lane & 15)) * ASTR + ks * 32 + (lane >> 4) * 16;
                ldm_x4(qf0[ks], ad);
                ldm_x4(qf1[ks], ad + AQ_BYTES);
            }
        }

        const uint32_t stg = sStage + (uint32_t)(kt & 1) * ASTAGE;
        const int k0 = kt * 64;
        const bool skip = (k0 > q0 + wm + 15);
        if (!skip) {
            // ---- scores S = Q K^T (bf16x3) ----
            float s[8][4];
#pragma unroll
            for (int j = 0; j < 8; j++)
#pragma unroll
                for (int e = 0; e < 4; e++) s[j][e] = 0.0f;
#pragma unroll
            for (int ks = 0; ks < 4; ks++) {
#pragma unroll
                for (int nt = 0; nt < 4; nt++) {
                    const uint32_t ad =
                        stg + (nt * 16 + (lane & 15)) * ASTR + ks * 32 + (lane >> 4) * 16;
                    uint32_t r4[4], r5[4];
                    ldm_x4(r4, ad);                 // K hi
                    ldm_x4(r5, ad + AKV_BYTES);     // K lo
                    uint32_t b00[2] = {r4[0], r4[2]}, b01[2] = {r4[1], r4[3]};
                    uint32_t b10[2] = {r5[0], r5[2]}, b11[2] = {r5[1], r5[3]};
                    mma16816(s[nt * 2],     qf0[ks], b00);
                    mma16816(s[nt * 2],     qf1[ks], b00);
                    mma16816(s[nt * 2],     qf0[ks], b10);
                    mma16816(s[nt * 2 + 1], qf0[ks], b01);
                    mma16816(s[nt * 2 + 1], qf1[ks], b01);
                    mma16816(s[nt * 2 + 1], qf0[ks], b11);
                }
            }

            // ---- mask + scale ----
            const int row0 = q0 + wm + (lane >> 2);
            const int row1 = row0 + 8;
            const bool needmask = (k0 + 63 > q0 + wm);
            if (needmask) {
#pragma unroll
                for (int j = 0; j < 8; j++) {
                    const int cbase = k0 + j * 8 + (lane & 3) * 2;
                    s[j][0] = (cbase     <= row0) ? s[j][0] * 0.125f : -INFINITY;
                    s[j][1] = (cbase + 1 <= row0) ? s[j][1] * 0.125f : -INFINITY;
                    s[j][2] = (cbase     <= row1) ? s[j][2] * 0.125f : -INFINITY;
                    s[j][3] = (cbase + 1 <= row1) ? s[j][3] * 0.125f : -INFINITY;
                }
            } else {
#pragma unroll
                for (int j = 0; j < 8; j++)
#pragma unroll
                    for (int e = 0; e < 4; e++) s[j][e] *= 0.125f;
            }

            // ---- online softmax ----
            float tm0 = -INFINITY, tm1 = -INFINITY;
#pragma unroll
            for (int j = 0; j < 8; j++) {
                tm0 = fmaxf(tm0, fmaxf(s[j][0], s[j][1]));
                tm1 = fmaxf(tm1, fmaxf(s[j][2], s[j][3]));
            }
            tm0 = fmaxf(tm0, __shfl_xor_sync(0xffffffffu, tm0, 1));
            tm0 = fmaxf(tm0, __shfl_xor_sync(0xffffffffu, tm0, 2));
            tm1 = fmaxf(tm1, __shfl_xor_sync(0xffffffffu, tm1, 1));
            tm1 = fmaxf(tm1, __shfl_xor_sync(0xffffffffu, tm1, 2));
            const float mn0 = fmaxf(mi0, tm0);
            const float mn1 = fmaxf(mi1, tm1);
            const float c0 = __expf(mi0 - mn0);
            const float c1 = __expf(mi1 - mn1);
            float ls0 = 0.0f, ls1 = 0.0f;
#pragma unroll
            for (int j = 0; j < 8; j++) {
                s[j][0] = __expf(s[j][0] - mn0);
                s[j][1] = __expf(s[j][1] - mn0);
                s[j][2] = __expf(s[j][2] - mn1);
                s[j][3] = __expf(s[j][3] - mn1);
                ls0 += s[j][0] + s[j][1];
                ls1 += s[j][2] + s[j][3];
            }
            ls0 += __shfl_xor_sync(0xffffffffu, ls0, 1);
            ls0 += __shfl_xor_sync(0xffffffffu, ls0, 2);
            ls1 += __shfl_xor_sync(0xffffffffu, ls1, 1);
            ls1 += __shfl_xor_sync(0xffffffffu, ls1, 2);
            li0 = li0 * c0 + ls0;
            li1 = li1 * c1 + ls1;
            mi0 = mn0; mi1 = mn1;
#pragma unroll
            for (int j = 0; j < 8; j++) {
                acc[j][0] *= c0; acc[j][1] *= c0;
                acc[j][2] *= c1; acc[j][3] *= c1;
            }

            // ---- PV: single fp16 MMA per fragment ----
#pragma unroll
            for (int ks = 0; ks < 4; ks++) {
                uint32_t A[4];
                A[0] = packh2(s[2 * ks][0],     s[2 * ks][1]);
                A[1] = packh2(s[2 * ks][2],     s[2 * ks][3]);
                A[2] = packh2(s[2 * ks + 1][0], s[2 * ks + 1][1]);
                A[3] = packh2(s[2 * ks + 1][2], s[2 * ks + 1][3]);
#pragma unroll
                for (int dvt = 0; dvt < 4; dvt++) {
                    const uint32_t ad = stg + 2 * AKV_BYTES +
                        (ks * 16 + (lane & 15)) * ASTR +
                        dvt * 32 + (lane >> 4) * 16;
                    uint32_t r4[4];
                    ldm_x4_t(r4, ad);               // V fp16 (transposed)
                    uint32_t vba[2] = {r4[0], r4[1]}, vbb[2] = {r4[2], r4[3]};
                    mma16816h(acc[2 * dvt],     A, vba);
                    mma16816h(acc[2 * dvt + 1], A, vbb);
                }
            }
        }
        __syncthreads();
    }

    // ---- epilogue: O rows -> split bf16 gO0/gO1 ----
    const float inv0 = 1.0f / li0;
    const float inv1 = 1.0f / li1;
    const int row0 = q0 + wm + (lane >> 2);
    const int row1 = row0 + 8;
    const size_t ob0 = ((size_t)b * SEQ + row0) * DIM + h * DH;
    const size_t ob1 = ((size_t)b * SEQ + row1) * DIM + h * DH;
#pragma unroll
    for (int j = 0; j < 8; j++) {
        const int dv = j * 8 + (lane & 3) * 2;
        uint32_t hi, lo;
        split2(acc[j][0] * inv0, acc[j][1] * inv0, hi, lo);
        *(uint32_t*)(gO0 + ob0 + dv) = hi;
        *(uint32_t*)(gO1 + ob0 + dv) = lo;
        split2(acc[j][2] * inv1, acc[j][3] * inv1, hi, lo);
        *(uint32_t*)(gO0 + ob1 + dv) = hi;
        *(uint32_t*)(gO1 + ob1 + dv) = lo;
    }
}

// ---------------------------------------------------------------------------
// kernel_launch
// ---------------------------------------------------------------------------
extern "C" void kernel_launch(void* const* d_in, const int* in_sizes, int n_in,
                              void* d_out, int out_size) {
    const float* x  = (const float*)d_in[0];
    // d_in[1] = causal mask (structure known, unused)
    const float* Wq = (const float*)d_in[2];
    const float* Wk = (const float*)d_in[3];
    const float* Wv = (const float*)d_in[4];
    const float* Wo = (const float*)d_in[5];
    float* out = (float*)d_out;

    cudaFuncSetAttribute(hmma_gemm<0>, cudaFuncAttributeMaxDynamicSharedMemorySize, SMEM_DYN);
    cudaFuncSetAttribute(hmma_gemm<1>, cudaFuncAttributeMaxDynamicSharedMemorySize, SMEM_DYN);
    cudaFuncSetAttribute(attn_mma, cudaFuncAttributeMaxDynamicSharedMemorySize, ATTN_SMEM);

    split_x_kernel<<<(MTOT * DIM / 4) / 256, 256>>>(x);
    prep_w_kernel<<<dim3(DIM / 32, DIM / 32, 4), 256>>>(Wq, Wk, Wv, Wo);

    hmma_gemm<1><<<dim3(DIM / 128, MTOT / 128, 3), 256, SMEM_DYN>>>(nullptr);

    attn_mma<<<dim3(SEQ / 128, HEADS, BB), 256, ATTN_SMEM>>>();

    hmma_gemm<0><<<dim3(DIM / 128, MTOT / 128, 1), 256, SMEM_DYN>>>(out);
}

// round 8
// speedup vs baseline: 3.9209x; 1.0715x over previous
#include <cuda_runtime.h>
#include <cuda_bf16.h>
#include <cuda_fp16.h>
#include <math.h>
#include <stdint.h>

#define BB    2
#define SEQ   2048
#define DIM   1024
#define HEADS 16
#define DH    64
#define MTOT  (BB * SEQ)   // 4096

// ---------------------------------------------------------------------------
// Scratch (device globals: allocation-free, harness-safe)
// ---------------------------------------------------------------------------
__device__ __align__(16) __nv_bfloat16 gX0[(size_t)MTOT * DIM];
__device__ __align__(16) __nv_bfloat16 gX1[(size_t)MTOT * DIM];
__device__ __align__(16) __nv_bfloat16 gW0[(size_t)4 * DIM * DIM];
__device__ __align__(16) __nv_bfloat16 gW1[(size_t)4 * DIM * DIM];
__device__ __align__(16) __half        gQh0[(size_t)MTOT * DIM]; // Q fp16 hi
__device__ __align__(16) __half        gQh1[(size_t)MTOT * DIM]; // Q fp16 lo
__device__ __align__(16) __half        gKh[(size_t)MTOT * DIM];  // K fp16
__device__ __align__(16) __half        gVh[(size_t)MTOT * DIM];  // V fp16
__device__ __align__(16) __nv_bfloat16 gO0[(size_t)MTOT * DIM];  // [m][k]
__device__ __align__(16) __nv_bfloat16 gO1[(size_t)MTOT * DIM];

// ---------------------------------------------------------------------------
// PTX helpers (sm_80+ baseline)
// ---------------------------------------------------------------------------
__device__ __forceinline__ uint32_t smem_u32(const void* p) {
    uint32_t a;
    asm("{ .reg .u64 t; cvta.to.shared.u64 t, %1; cvt.u32.u64 %0, t; }"
        : "=r"(a) : "l"(p));
    return a;
}
__device__ __forceinline__ void ldm_x4(uint32_t* r, uint32_t addr) {
    asm volatile("ldmatrix.sync.aligned.m8n8.x4.shared.b16 {%0,%1,%2,%3}, [%4];"
                 : "=r"(r[0]), "=r"(r[1]), "=r"(r[2]), "=r"(r[3]) : "r"(addr));
}
__device__ __forceinline__ void ldm_x4_t(uint32_t* r, uint32_t addr) {
    asm volatile("ldmatrix.sync.aligned.m8n8.x4.trans.shared.b16 {%0,%1,%2,%3}, [%4];"
                 : "=r"(r[0]), "=r"(r[1]), "=r"(r[2]), "=r"(r[3]) : "r"(addr));
}
__device__ __forceinline__ void mma16816(float* d, const uint32_t* a,
                                         const uint32_t* b) {
    asm volatile(
        "mma.sync.aligned.m16n8k16.row.col.f32.bf16.bf16.f32 "
        "{%0,%1,%2,%3}, {%4,%5,%6,%7}, {%8,%9}, {%0,%1,%2,%3};"
        : "+f"(d[0]), "+f"(d[1]), "+f"(d[2]), "+f"(d[3])
        : "r"(a[0]), "r"(a[1]), "r"(a[2]), "r"(a[3]), "r"(b[0]), "r"(b[1]));
}
__device__ __forceinline__ void mma16816h(float* d, const uint32_t* a,
                                          const uint32_t* b) {
    asm volatile(
        "mma.sync.aligned.m16n8k16.row.col.f32.f16.f16.f32 "
        "{%0,%1,%2,%3}, {%4,%5,%6,%7}, {%8,%9}, {%0,%1,%2,%3};"
        : "+f"(d[0]), "+f"(d[1]), "+f"(d[2]), "+f"(d[3])
        : "r"(a[0]), "r"(a[1]), "r"(a[2]), "r"(a[3]), "r"(b[0]), "r"(b[1]));
}
__device__ __forceinline__ void cp16(uint32_t s, const void* g) {
    asm volatile("cp.async.cg.shared.global [%0], [%1], 16;" :: "r"(s), "l"(g));
}
#define CP_COMMIT() asm volatile("cp.async.commit_group;" ::: "memory")
#define CP_WAIT(n)  asm volatile("cp.async.wait_group %0;" :: "n"(n) : "memory")

__device__ __forceinline__ uint32_t packbf2(float a, float b) {
    __nv_bfloat162 t = __floats2bfloat162_rn(a, b);
    return *(uint32_t*)&t;
}
__device__ __forceinline__ uint32_t packh2(float a, float b) {
    __half2 t = __floats2half2_rn(a, b);
    return *(uint32_t*)&t;
}
__device__ __forceinline__ void split2(float a, float b, uint32_t& hi, uint32_t& lo) {
    const __nv_bfloat16 ha = __float2bfloat16_rn(a);
    const __nv_bfloat16 hb = __float2bfloat16_rn(b);
    __nv_bfloat162 t; t.x = ha; t.y = hb;
    hi = *(uint32_t*)&t;
    lo = packbf2(a - __bfloat162float(ha), b - __bfloat162float(hb));
}
__device__ __forceinline__ void splith2(float a, float b, uint32_t& hi, uint32_t& lo) {
    const __half ha = __float2half_rn(a);
    const __half hb = __float2half_rn(b);
    __half2 t; t.x = ha; t.y = hb;
    hi = *(uint32_t*)&t;
    lo = packh2(a - __half2float(ha), b - __half2float(hb));
}

// ---------------------------------------------------------------------------
// HMMA bf16x3 GEMM; MODE 1 epilogue emits fp16 pair Q, fp16 K, fp16 V
// ---------------------------------------------------------------------------
#define AST   80
#define ARR   10240
#define STG   40960
#define SMEM_DYN (2 * STG)
#define NSLAB (DIM / 32)

template <int MODE>
__global__ __launch_bounds__(256) void hmma_gemm(float* __restrict__ outp) {
    extern __shared__ char smem_raw[];
    const uint32_t sbase = smem_u32(smem_raw);
    const int tid  = threadIdx.x;
    const int lane = tid & 31;
    const int wid  = tid >> 5;
    const int z    = blockIdx.z;
    const int m0   = blockIdx.y * 128;
    const int n0   = blockIdx.x * 128;

    const __nv_bfloat16* A0g = (MODE == 1) ? gX0 : gO0;
    const __nv_bfloat16* A1g = (MODE == 1) ? gX1 : gO1;
    const size_t woff = (MODE == 1) ? (size_t)z * DIM * DIM : (size_t)3 * DIM * DIM;
    const __nv_bfloat16* B0g = gW0 + woff;
    const __nv_bfloat16* B1g = gW1 + woff;

    const int ldr = tid >> 2;
    const int ldc = tid & 3;

    float acc[2][8][4];
#pragma unroll
    for (int mi = 0; mi < 2; mi++)
#pragma unroll
        for (int ni = 0; ni < 8; ni++)
#pragma unroll
            for (int u = 0; u < 4; u++) acc[mi][ni][u] = 0.0f;

    const int wm = (wid & 3) * 32;
    const int wn = (wid >> 2) * 64;
    const int lrow  = lane & 15;
    const int lcolb = (lane >> 4) * 16;

#define ISSUE_SLAB(s) do {                                                    \
        const int _st = (s) & 1;                                              \
        const int _k0 = (s) * 32;                                             \
        _Pragma("unroll")                                                     \
        for (int t = 0; t < 2; t++) {                                         \
            const int r = ldr + t * 64;                                       \
            const size_t ga = (size_t)(m0 + r) * DIM + _k0 + ldc * 8;         \
            const uint32_t sa = sbase + _st * STG + r * AST + ldc * 16;       \
            cp16(sa, A0g + ga);                                               \
            cp16(sa + ARR, A1g + ga);                                         \
            const size_t gb = (size_t)(n0 + r) * DIM + _k0 + ldc * 8;         \
            const uint32_t sb = sbase + _st * STG + 2 * ARR + r * AST + ldc * 16; \
            cp16(sb, B0g + gb);                                               \
            cp16(sb + ARR, B1g + gb);                                         \
        }                                                                     \
        CP_COMMIT();                                                          \
    } while (0)

    ISSUE_SLAB(0);
    for (int s = 0; s < NSLAB; s++) {
        if (s + 1 < NSLAB) { ISSUE_SLAB(s + 1); CP_WAIT(1); }
        else               { CP_WAIT(0); }
        __syncthreads();

        const uint32_t stoff = (uint32_t)(s & 1) * STG;
#pragma unroll
        for (int j = 0; j < 2; j++) {
            const uint32_t kb = j * 32 + lcolb;
            uint32_t a0f[2][4], a1f[2][4];
#pragma unroll
            for (int mi = 0; mi < 2; mi++) {
                const uint32_t ad = sbase + stoff + (wm + mi * 16 + lrow) * AST + kb;
                ldm_x4(a0f[mi], ad);
                ldm_x4(a1f[mi], ad + ARR);
            }
            uint32_t b0f[8][2], b1f[8][2];
#pragma unroll
            for (int nt = 0; nt < 4; nt++) {
                const uint32_t bd = sbase + stoff + 2 * ARR + (wn + nt * 16 + lrow) * AST + kb;
                uint32_t r4[4];
                ldm_x4(r4, bd);
                b0f[nt * 2][0]     = r4[0]; b0f[nt * 2][1]     = r4[2];
                b0f[nt * 2 + 1][0] = r4[1]; b0f[nt * 2 + 1][1] = r4[3];
                ldm_x4(r4, bd + ARR);
                b1f[nt * 2][0]     = r4[0]; b1f[nt * 2][1]     = r4[2];
                b1f[nt * 2 + 1][0] = r4[1]; b1f[nt * 2 + 1][1] = r4[3];
            }
#pragma unroll
            for (int mi = 0; mi < 2; mi++)
#pragma unroll
                for (int ni = 0; ni < 8; ni++) {
                    mma16816(acc[mi][ni], a0f[mi], b0f[ni]);
                    mma16816(acc[mi][ni], a0f[mi], b1f[ni]);
                    mma16816(acc[mi][ni], a1f[mi], b0f[ni]);
                }
        }
        __syncthreads();
    }

#pragma unroll
    for (int mi = 0; mi < 2; mi++)
#pragma unroll
        for (int ni = 0; ni < 8; ni++) {
            const int cc = n0 + wn + ni * 8 + (lane & 3) * 2;
#pragma unroll
            for (int h2 = 0; h2 < 2; h2++) {
                const int m = m0 + wm + mi * 16 + (lane >> 2) + h2 * 8;
                const float ox = acc[mi][ni][h2 * 2];
                const float oy = acc[mi][ni][h2 * 2 + 1];
                if (MODE == 0) {
                    *(float2*)(outp + (size_t)m * DIM + cc) = make_float2(ox, oy);
                } else {
                    const int b = m >> 11, sq = m & (SEQ - 1);
                    const int h = cc >> 6, d0 = cc & 63;
                    const size_t idx = ((size_t)(b * HEADS + h) * SEQ + sq) * DH + d0;
                    if (z == 0) {
                        uint32_t hi, lo;
                        splith2(ox, oy, hi, lo);
                        *(uint32_t*)(gQh0 + idx) = hi;
                        *(uint32_t*)(gQh1 + idx) = lo;
                    } else if (z == 1) {
                        *(uint32_t*)(gKh + idx) = packh2(ox, oy);
                    } else {
                        *(uint32_t*)(gVh + idx) = packh2(ox, oy);
                    }
                }
            }
        }
}

// ---------------------------------------------------------------------------
// Prep kernels
// ---------------------------------------------------------------------------
__global__ __launch_bounds__(256) void split_x_kernel(const float* __restrict__ x) {
    const int i = blockIdx.x * 256 + threadIdx.x;
    const float4 v = ((const float4*)x)[i];
    union { __nv_bfloat16 h[4]; uint2 u; } H, L;
    const float f[4] = {v.x, v.y, v.z, v.w};
#pragma unroll
    for (int j = 0; j < 4; j++) {
        H.h[j] = __float2bfloat16_rn(f[j]);
        L.h[j] = __float2bfloat16_rn(f[j] - __bfloat162float(H.h[j]));
    }
    *(uint2*)(gX0 + (size_t)i * 4) = H.u;
    *(uint2*)(gX1 + (size_t)i * 4) = L.u;
}

__global__ __launch_bounds__(256) void prep_w_kernel(const float* __restrict__ Wq,
                                                     const float* __restrict__ Wk,
                                                     const float* __restrict__ Wv,
                                                     const float* __restrict__ Wo) {
    __shared__ float tile[32][33];
    const int z = blockIdx.z;
    const float* W = (z == 0) ? Wq : (z == 1) ? Wk : (z == 2) ? Wv : Wo;
    __nv_bfloat16* T0 = gW0 + (size_t)z * DIM * DIM;
    __nv_bfloat16* T1 = gW1 + (size_t)z * DIM * DIM;
    const int n0 = blockIdx.x * 32, k0 = blockIdx.y * 32;
    const int tx = threadIdx.x & 31, ty = threadIdx.x >> 5;
#pragma unroll
    for (int i = 0; i < 4; i++)
        tile[ty + 8 * i][tx] = W[(size_t)(k0 + ty + 8 * i) * DIM + n0 + tx];
    __syncthreads();
#pragma unroll
    for (int i = 0; i < 4; i++) {
        const int n = n0 + ty + 8 * i;
        const float v = tile[tx][ty + 8 * i];
        const __nv_bfloat16 hi = __float2bfloat16_rn(v);
        T0[(size_t)n * DIM + k0 + tx] = hi;
        T1[(size_t)n * DIM + k0 + tx] = __float2bfloat16_rn(v - __bfloat162float(hi));
    }
}

// ---------------------------------------------------------------------------
// Flash attention: Q fp16x2, K/V fp16 single. Causal.
// q-tile 128 (8 warps x 16 rows), kv-tile 64, 3-stage cp.async pipeline.
// Smem: [Qh0 18432][Qh1 18432][stage i: Kh, Vh @9216 each] x 3
// ---------------------------------------------------------------------------
#define ASTR       144
#define AQ_BYTES   (128 * ASTR)      // 18432
#define AKV_BYTES  (64 * ASTR)       // 9216
#define ASTAGE     (2 * AKV_BYTES)   // 18432
#define ATTN_SMEM  (2 * AQ_BYTES + 3 * ASTAGE)   // 92160

__global__ __launch_bounds__(256) void attn_mma() {
    extern __shared__ char smem_raw[];
    const uint32_t sb = smem_u32(smem_raw);
    const int tid  = threadIdx.x;
    const int lane = tid & 31;
    const int wid  = tid >> 5;
    const int qt   = (int)gridDim.x - 1 - (int)blockIdx.x;   // heavy tiles first
    const int h    = blockIdx.y;
    const int b    = blockIdx.z;
    const int q0   = qt * 128;
    const size_t hoff = (size_t)(b * HEADS + h) * SEQ * DH;
    const __half* Q0g = gQh0 + hoff;
    const __half* Q1g = gQh1 + hoff;
    const __half* Kg  = gKh + hoff;
    const __half* Vg  = gVh + hoff;

    const uint32_t sStage = sb + 2 * AQ_BYTES;

    // Q loads: 2 arrays x 128 rows x 8 chunks = 8 per thread
#pragma unroll
    for (int t = 0; t < 8; t++) {
        const int v = tid + t * 256;
        const int arr = v >> 10;
        const int rem = v & 1023;
        const int r = rem >> 3, c = rem & 7;
        const __half* src = (arr ? Q1g : Q0g) + (size_t)(q0 + r) * DH + c * 8;
        cp16(sb + arr * AQ_BYTES + r * ASTR + c * 16, src);
    }

    // KV: K + V fp16: 2 arrays x 64 rows x 8 chunks = 4 per thread
#define ISSUE_KV(kt, sidx) do {                                                \
        const int _k0 = (kt) * 64;                                             \
        const uint32_t _dst = sStage + (uint32_t)(sidx) * ASTAGE;               \
        _Pragma("unroll")                                                       \
        for (int t = 0; t < 4; t++) {                                           \
            const int v = tid + t * 256;                                        \
            const int arr = v >> 9;                                             \
            const int rem = v & 511;                                            \
            const int r = rem >> 3, c = rem & 7;                                \
            const __half* src = ((arr == 0) ? Kg : Vg)                          \
                + (size_t)(_k0 + r) * DH + c * 8;                               \
            cp16(_dst + arr * AKV_BYTES + r * ASTR + c * 16, src);              \
        }                                                                       \
        CP_COMMIT();                                                            \
    } while (0)

    const int nkt = 2 * (qt + 1);   // >= 2 always
    ISSUE_KV(0, 0);   // shares first commit group with Q
    ISSUE_KV(1, 1);

    const int wm = wid * 16;
    float acc[8][4];
#pragma unroll
    for (int j = 0; j < 8; j++)
#pragma unroll
        for (int e = 0; e < 4; e++) acc[j][e] = 0.0f;
    float mi0 = -INFINITY, mi1 = -INFINITY, li0 = 0.0f, li1 = 0.0f;
    uint32_t qf0[4][4], qf1[4][4];

    int cur = 0;
    for (int kt = 0; kt < nkt; kt++) {
        if (kt + 2 < nkt) {
            int nx = cur + 2; if (nx >= 3) nx -= 3;
            ISSUE_KV(kt + 2, nx);
            CP_WAIT(2);
        } else {
            CP_WAIT(0);
        }
        __syncthreads();

        if (kt == 0) {
#pragma unroll
            for (int ks = 0; ks < 4; ks++) {
                const uint32_t ad =
                    sb + (wm + (lane & 15)) * ASTR + ks * 32 + (lane >> 4) * 16;
                ldm_x4(qf0[ks], ad);
                ldm_x4(qf1[ks], ad + AQ_BYTES);
            }
        }

        const uint32_t stg = sStage + (uint32_t)cur * ASTAGE;
        const int k0 = kt * 64;
        const bool skip = (k0 > q0 + wm + 15);
        if (!skip) {
            // ---- scores S = Q K^T (Q fp16x2, K fp16) ----
            float s[8][4];
#pragma unroll
            for (int j = 0; j < 8; j++)
#pragma unroll
                for (int e = 0; e < 4; e++) s[j][e] = 0.0f;
#pragma unroll
            for (int ks = 0; ks < 4; ks++) {
#pragma unroll
                for (int nt = 0; nt < 4; nt++) {
                    const uint32_t ad =
                        stg + (nt * 16 + (lane & 15)) * ASTR + ks * 32 + (lane >> 4) * 16;
                    uint32_t r4[4];
                    ldm_x4(r4, ad);                 // K fp16
                    uint32_t b0[2] = {r4[0], r4[2]}, b1[2] = {r4[1], r4[3]};
                    mma16816h(s[nt * 2],     qf0[ks], b0);
                    mma16816h(s[nt * 2],     qf1[ks], b0);
                    mma16816h(s[nt * 2 + 1], qf0[ks], b1);
                    mma16816h(s[nt * 2 + 1], qf1[ks], b1);
                }
            }

            // ---- mask + scale ----
            const int row0 = q0 + wm + (lane >> 2);
            const int row1 = row0 + 8;
            const bool needmask = (k0 + 63 > q0 + wm);
            if (needmask) {
#pragma unroll
                for (int j = 0; j < 8; j++) {
                    const int cbase = k0 + j * 8 + (lane & 3) * 2;
                    s[j][0] = (cbase     <= row0) ? s[j][0] * 0.125f : -INFINITY;
                    s[j][1] = (cbase + 1 <= row0) ? s[j][1] * 0.125f : -INFINITY;
                    s[j][2] = (cbase     <= row1) ? s[j][2] * 0.125f : -INFINITY;
                    s[j][3] = (cbase + 1 <= row1) ? s[j][3] * 0.125f : -INFINITY;
                }
            } else {
#pragma unroll
                for (int j = 0; j < 8; j++)
#pragma unroll
                    for (int e = 0; e < 4; e++) s[j][e] *= 0.125f;
            }

            // ---- online softmax ----
            float tm0 = -INFINITY, tm1 = -INFINITY;
#pragma unroll
            for (int j = 0; j < 8; j++) {
                tm0 = fmaxf(tm0, fmaxf(s[j][0], s[j][1]));
                tm1 = fmaxf(tm1, fmaxf(s[j][2], s[j][3]));
            }
            tm0 = fmaxf(tm0, __shfl_xor_sync(0xffffffffu, tm0, 1));
            tm0 = fmaxf(tm0, __shfl_xor_sync(0xffffffffu, tm0, 2));
            tm1 = fmaxf(tm1, __shfl_xor_sync(0xffffffffu, tm1, 1));
            tm1 = fmaxf(tm1, __shfl_xor_sync(0xffffffffu, tm1, 2));
            const float mn0 = fmaxf(mi0, tm0);
            const float mn1 = fmaxf(mi1, tm1);
            const float c0 = __expf(mi0 - mn0);
            const float c1 = __expf(mi1 - mn1);
            float ls0 = 0.0f, ls1 = 0.0f;
#pragma unroll
            for (int j = 0; j < 8; j++) {
                s[j][0] = __expf(s[j][0] - mn0);
                s[j][1] = __expf(s[j][1] - mn0);
                s[j][2] = __expf(s[j][2] - mn1);
                s[j][3] = __expf(s[j][3] - mn1);
                ls0 += s[j][0] + s[j][1];
                ls1 += s[j][2] + s[j][3];
            }
            ls0 += __shfl_xor_sync(0xffffffffu, ls0, 1);
            ls0 += __shfl_xor_sync(0xffffffffu, ls0, 2);
            ls1 += __shfl_xor_sync(0xffffffffu, ls1, 1);
            ls1 += __shfl_xor_sync(0xffffffffu, ls1, 2);
            li0 = li0 * c0 + ls0;
            li1 = li1 * c1 + ls1;
            mi0 = mn0; mi1 = mn1;
#pragma unroll
            for (int j = 0; j < 8; j++) {
                acc[j][0] *= c0; acc[j][1] *= c0;
                acc[j][2] *= c1; acc[j][3] *= c1;
            }

            // ---- PV: single fp16 MMA per fragment ----
#pragma unroll
            for (int ks = 0; ks < 4; ks++) {
                uint32_t A[4];
                A[0] = packh2(s[2 * ks][0],     s[2 * ks][1]);
                A[1] = packh2(s[2 * ks][2],     s[2 * ks][3]);
                A[2] = packh2(s[2 * ks + 1][0], s[2 * ks + 1][1]);
                A[3] = packh2(s[2 * ks + 1][2], s[2 * ks + 1][3]);
#pragma unroll
                for (int dvt = 0; dvt < 4; dvt++) {
                    const uint32_t ad = stg + AKV_BYTES +
                        (ks * 16 + (lane & 15)) * ASTR +
                        dvt * 32 + (lane >> 4) * 16;
                    uint32_t r4[4];
                    ldm_x4_t(r4, ad);               // V fp16 (transposed)
                    uint32_t vba[2] = {r4[0], r4[1]}, vbb[2] = {r4[2], r4[3]};
                    mma16816h(acc[2 * dvt],     A, vba);
                    mma16816h(acc[2 * dvt + 1], A, vbb);
                }
            }
        }
        __syncthreads();
        if (++cur == 3) cur = 0;
    }

    // ---- epilogue: O rows -> split bf16 gO0/gO1 ----
    const float inv0 = 1.0f / li0;
    const float inv1 = 1.0f / li1;
    const int row0 = q0 + wm + (lane >> 2);
    const int row1 = row0 + 8;
    const size_t ob0 = ((size_t)b * SEQ + row0) * DIM + h * DH;
    const size_t ob1 = ((size_t)b * SEQ + row1) * DIM + h * DH;
#pragma unroll
    for (int j = 0; j < 8; j++) {
        const int dv = j * 8 + (lane & 3) * 2;
        uint32_t hi, lo;
        split2(acc[j][0] * inv0, acc[j][1] * inv0, hi, lo);
        *(uint32_t*)(gO0 + ob0 + dv) = hi;
        *(uint32_t*)(gO1 + ob0 + dv) = lo;
        split2(acc[j][2] * inv1, acc[j][3] * inv1, hi, lo);
        *(uint32_t*)(gO0 + ob1 + dv) = hi;
        *(uint32_t*)(gO1 + ob1 + dv) = lo;
    }
}

// ---------------------------------------------------------------------------
// kernel_launch
// ---------------------------------------------------------------------------
extern "C" void kernel_launch(void* const* d_in, const int* in_sizes, int n_in,
                              void* d_out, int out_size) {
    const float* x  = (const float*)d_in[0];
    // d_in[1] = causal mask (structure known, unused)
    const float* Wq = (const float*)d_in[2];
    const float* Wk = (const float*)d_in[3];
    const float* Wv = (const float*)d_in[4];
    const float* Wo = (const float*)d_in[5];
    float* out = (float*)d_out;

    cudaFuncSetAttribute(hmma_gemm<0>, cudaFuncAttributeMaxDynamicSharedMemorySize, SMEM_DYN);
    cudaFuncSetAttribute(hmma_gemm<1>, cudaFuncAttributeMaxDynamicSharedMemorySize, SMEM_DYN);
    cudaFuncSetAttribute(attn_mma, cudaFuncAttributeMaxDynamicSharedMemorySize, ATTN_SMEM);

    split_x_kernel<<<(MTOT * DIM / 4) / 256, 256>>>(x);
    prep_w_kernel<<<dim3(DIM / 32, DIM / 32, 4), 256>>>(Wq, Wk, Wv, Wo);

    hmma_gemm<1><<<dim3(DIM / 128, MTOT / 128, 3), 256, SMEM_DYN>>>(nullptr);

    attn_mma<<<dim3(SEQ / 128, HEADS, BB), 256, ATTN_SMEM>>>();

    hmma_gemm<0><<<dim3(DIM / 128, MTOT / 128, 1), 256, SMEM_DYN>>>(out);
}

// round 9
// speedup vs baseline: 7.1936x; 1.8347x over previous
#include <cuda_runtime.h>
#include <cuda_fp16.h>
#include <math.h>
#include <stdint.h>

#define BB    2
#define SEQ   2048
#define DIM   1024
#define HEADS 16
#define DH    64
#define MTOT  (BB * SEQ)   // 4096

// ---------------------------------------------------------------------------
// Scratch (device globals: allocation-free, harness-safe) — all fp16
// ---------------------------------------------------------------------------
__device__ __align__(16) __half gXh[(size_t)MTOT * DIM];      // x fp16 [m][k]
__device__ __align__(16) __half gWh[(size_t)4 * DIM * DIM];   // W^T fp16 [w][n][k]
__device__ __align__(16) __half gQh[(size_t)MTOT * DIM];      // [B,H,S,DH]
__device__ __align__(16) __half gKh[(size_t)MTOT * DIM];
__device__ __align__(16) __half gVh[(size_t)MTOT * DIM];
__device__ __align__(16) __half gOh[(size_t)MTOT * DIM];      // attn out [m][k]

// ---------------------------------------------------------------------------
// PTX helpers (sm_80+ baseline)
// ---------------------------------------------------------------------------
__device__ __forceinline__ uint32_t smem_u32(const void* p) {
    uint32_t a;
    asm("{ .reg .u64 t; cvta.to.shared.u64 t, %1; cvt.u32.u64 %0, t; }"
        : "=r"(a) : "l"(p));
    return a;
}
__device__ __forceinline__ void ldm_x4(uint32_t* r, uint32_t addr) {
    asm volatile("ldmatrix.sync.aligned.m8n8.x4.shared.b16 {%0,%1,%2,%3}, [%4];"
                 : "=r"(r[0]), "=r"(r[1]), "=r"(r[2]), "=r"(r[3]) : "r"(addr));
}
__device__ __forceinline__ void ldm_x4_t(uint32_t* r, uint32_t addr) {
    asm volatile("ldmatrix.sync.aligned.m8n8.x4.trans.shared.b16 {%0,%1,%2,%3}, [%4];"
                 : "=r"(r[0]), "=r"(r[1]), "=r"(r[2]), "=r"(r[3]) : "r"(addr));
}
__device__ __forceinline__ void mma16816h(float* d, const uint32_t* a,
                                          const uint32_t* b) {
    asm volatile(
        "mma.sync.aligned.m16n8k16.row.col.f32.f16.f16.f32 "
        "{%0,%1,%2,%3}, {%4,%5,%6,%7}, {%8,%9}, {%0,%1,%2,%3};"
        : "+f"(d[0]), "+f"(d[1]), "+f"(d[2]), "+f"(d[3])
        : "r"(a[0]), "r"(a[1]), "r"(a[2]), "r"(a[3]), "r"(b[0]), "r"(b[1]));
}
__device__ __forceinline__ void cp16(uint32_t s, const void* g) {
    asm volatile("cp.async.cg.shared.global [%0], [%1], 16;" :: "r"(s), "l"(g));
}
#define CP_COMMIT() asm volatile("cp.async.commit_group;" ::: "memory")
#define CP_WAIT(n)  asm volatile("cp.async.wait_group %0;" :: "n"(n) : "memory")

__device__ __forceinline__ uint32_t packh2(float a, float b) {
    __half2 t = __floats2half2_rn(a, b);
    return *(uint32_t*)&t;
}

// ---------------------------------------------------------------------------
// Pure fp16 HMMA GEMM: C[m][n] = sum_k A[m][k]*W[k][n]
// Block 128x128, BK=32, 8 warps (4m x 2n), 3-stage cp.async pipeline.
// MODE 1: A=gXh, B=gWh[z], scatter fp16 into gQh/gKh/gVh (z=0/1/2)
// MODE 0: A=gOh, B=gWh[3], row-major fp32 store to outp
// ---------------------------------------------------------------------------
#define AST   80          // smem row stride bytes (32 fp16 = 64B data + pad)
#define ARR   10240       // 128 rows * 80
#define STGB  (2 * ARR)   // one stage: A, B
#define SMEM_DYN (3 * STGB)   // 61440
#define NSLAB (DIM / 32)  // 32

template <int MODE>
__global__ __launch_bounds__(256) void hmma_gemm(float* __restrict__ outp) {
    extern __shared__ char smem_raw[];
    const uint32_t sbase = smem_u32(smem_raw);
    const int tid  = threadIdx.x;
    const int lane = tid & 31;
    const int wid  = tid >> 5;
    const int z    = blockIdx.z;
    const int m0   = blockIdx.y * 128;
    const int n0   = blockIdx.x * 128;

    const __half* Ag = (MODE == 1) ? gXh : gOh;
    const size_t woff = (MODE == 1) ? (size_t)z * DIM * DIM : (size_t)3 * DIM * DIM;
    const __half* Bg = gWh + woff;

    float acc[2][8][4];
#pragma unroll
    for (int mi = 0; mi < 2; mi++)
#pragma unroll
        for (int ni = 0; ni < 8; ni++)
#pragma unroll
            for (int u = 0; u < 4; u++) acc[mi][ni][u] = 0.0f;

    const int wm = (wid & 3) * 32;
    const int wn = (wid >> 2) * 64;
    const int lrow  = lane & 15;
    const int lcolb = (lane >> 4) * 16;

    // slab loader: A + B, 128 rows x 4 x 16B each -> 4 cp16 per thread
#define ISSUE_SLAB(s, sidx) do {                                              \
        const int _k0 = (s) * 32;                                             \
        const uint32_t _dst = sbase + (uint32_t)(sidx) * STGB;                \
        _Pragma("unroll")                                                     \
        for (int t = 0; t < 2; t++) {                                         \
            const int v = tid + t * 256;                                      \
            const int r = v >> 2, c = v & 3;                                  \
            cp16(_dst + r * AST + c * 16,                                     \
                 Ag + (size_t)(m0 + r) * DIM + _k0 + c * 8);                  \
            cp16(_dst + ARR + r * AST + c * 16,                               \
                 Bg + (size_t)(n0 + r) * DIM + _k0 + c * 8);                  \
        }                                                                     \
        CP_COMMIT();                                                          \
    } while (0)

    ISSUE_SLAB(0, 0);
    ISSUE_SLAB(1, 1);

    int cur = 0;
    for (int s = 0; s < NSLAB; s++) {
        if (s + 2 < NSLAB) {
            int nx = cur + 2; if (nx >= 3) nx -= 3;
            ISSUE_SLAB(s + 2, nx);
            CP_WAIT(2);
        } else {
            CP_WAIT(0);
        }
        __syncthreads();

        const uint32_t stoff = (uint32_t)cur * STGB;
#pragma unroll
        for (int j = 0; j < 2; j++) {
            const uint32_t kb = j * 32 + lcolb;
            uint32_t af[2][4];
#pragma unroll
            for (int mi = 0; mi < 2; mi++)
                ldm_x4(af[mi], sbase + stoff + (wm + mi * 16 + lrow) * AST + kb);
            uint32_t bf[8][2];
#pragma unroll
            for (int nt = 0; nt < 4; nt++) {
                uint32_t r4[4];
                ldm_x4(r4, sbase + stoff + ARR + (wn + nt * 16 + lrow) * AST + kb);
                bf[nt * 2][0]     = r4[0]; bf[nt * 2][1]     = r4[2];
                bf[nt * 2 + 1][0] = r4[1]; bf[nt * 2 + 1][1] = r4[3];
            }
#pragma unroll
            for (int mi = 0; mi < 2; mi++)
#pragma unroll
                for (int ni = 0; ni < 8; ni++)
                    mma16816h(acc[mi][ni], af[mi], bf[ni]);
        }
        __syncthreads();
        if (++cur == 3) cur = 0;
    }

    // Epilogue
#pragma unroll
    for (int mi = 0; mi < 2; mi++)
#pragma unroll
        for (int ni = 0; ni < 8; ni++) {
            const int cc = n0 + wn + ni * 8 + (lane & 3) * 2;
#pragma unroll
            for (int h2 = 0; h2 < 2; h2++) {
                const int m = m0 + wm + mi * 16 + (lane >> 2) + h2 * 8;
                const float ox = acc[mi][ni][h2 * 2];
                const float oy = acc[mi][ni][h2 * 2 + 1];
                if (MODE == 0) {
                    *(float2*)(outp + (size_t)m * DIM + cc) = make_float2(ox, oy);
                } else {
                    const int b = m >> 11, sq = m & (SEQ - 1);
                    const int h = cc >> 6, d0 = cc & 63;
                    const size_t idx = ((size_t)(b * HEADS + h) * SEQ + sq) * DH + d0;
                    __half* G = (z == 0) ? gQh : (z == 1) ? gKh : gVh;
                    *(uint32_t*)(G + idx) = packh2(ox, oy);
                }
            }
        }
}

// ---------------------------------------------------------------------------
// Prep kernels: fp32 -> fp16 convert (x) and transpose+convert (W)
// ---------------------------------------------------------------------------
__global__ __launch_bounds__(256) void conv_x_kernel(const float* __restrict__ x) {
    const int i = blockIdx.x * 256 + threadIdx.x;   // one float4
    const float4 v = ((const float4*)x)[i];
    uint2 o;
    o.x = packh2(v.x, v.y);
    o.y = packh2(v.z, v.w);
    *(uint2*)(gXh + (size_t)i * 4) = o;
}

__global__ __launch_bounds__(256) void prep_w_kernel(const float* __restrict__ Wq,
                                                     const float* __restrict__ Wk,
                                                     const float* __restrict__ Wv,
                                                     const float* __restrict__ Wo) {
    __shared__ float tile[32][33];
    const int z = blockIdx.z;
    const float* W = (z == 0) ? Wq : (z == 1) ? Wk : (z == 2) ? Wv : Wo;
    __half* T = gWh + (size_t)z * DIM * DIM;
    const int n0 = blockIdx.x * 32, k0 = blockIdx.y * 32;
    const int tx = threadIdx.x & 31, ty = threadIdx.x >> 5;   // 32 x 8
#pragma unroll
    for (int i = 0; i < 4; i++)
        tile[ty + 8 * i][tx] = W[(size_t)(k0 + ty + 8 * i) * DIM + n0 + tx];
    __syncthreads();
#pragma unroll
    for (int i = 0; i < 4; i++) {
        const int n = n0 + ty + 8 * i;
        T[(size_t)n * DIM + k0 + tx] = __float2half_rn(tile[tx][ty + 8 * i]);
    }
}

// ---------------------------------------------------------------------------
// Flash attention: all fp16 operands, fp32 accum. Causal.
// q-tile 128 (8 warps x 16 rows), kv-tile 64, 3-stage cp.async pipeline.
// Smem: [Qh 18432][stage i: Kh, Vh @9216 each] x 3
// ---------------------------------------------------------------------------
#define ASTR       144
#define AQ_BYTES   (128 * ASTR)      // 18432
#define AKV_BYTES  (64 * ASTR)       // 9216
#define ASTAGE     (2 * AKV_BYTES)   // 18432
#define ATTN_SMEM  (AQ_BYTES + 3 * ASTAGE)   // 73728

__global__ __launch_bounds__(256) void attn_mma() {
    extern __shared__ char smem_raw[];
    const uint32_t sb = smem_u32(smem_raw);
    const int tid  = threadIdx.x;
    const int lane = tid & 31;
    const int wid  = tid >> 5;
    const int qt   = (int)gridDim.x - 1 - (int)blockIdx.x;   // heavy tiles first
    const int h    = blockIdx.y;
    const int b    = blockIdx.z;
    const int q0   = qt * 128;
    const size_t hoff = (size_t)(b * HEADS + h) * SEQ * DH;
    const __half* Qg = gQh + hoff;
    const __half* Kg = gKh + hoff;
    const __half* Vg = gVh + hoff;

    const uint32_t sStage = sb + AQ_BYTES;

    // Q loads: 128 rows x 8 chunks = 4 per thread
#pragma unroll
    for (int t = 0; t < 4; t++) {
        const int v = tid + t * 256;
        const int r = v >> 3, c = v & 7;
        cp16(sb + r * ASTR + c * 16, Qg + (size_t)(q0 + r) * DH + c * 8);
    }

    // KV: K + V fp16: 2 arrays x 64 rows x 8 chunks = 4 per thread
#define ISSUE_KV(kt, sidx) do {                                                \
        const int _k0 = (kt) * 64;                                             \
        const uint32_t _dst = sStage + (uint32_t)(sidx) * ASTAGE;               \
        _Pragma("unroll")                                                       \
        for (int t = 0; t < 4; t++) {                                           \
            const int v = tid + t * 256;                                        \
            const int arr = v >> 9;                                             \
            const int rem = v & 511;                                            \
            const int r = rem >> 3, c = rem & 7;                                \
            const __half* src = ((arr == 0) ? Kg : Vg)                          \
                + (size_t)(_k0 + r) * DH + c * 8;                               \
            cp16(_dst + arr * AKV_BYTES + r * ASTR + c * 16, src);              \
        }                                                                       \
        CP_COMMIT();                                                            \
    } while (0)

    const int nkt = 2 * (qt + 1);   // >= 2 always
    ISSUE_KV(0, 0);   // shares first commit group with Q
    ISSUE_KV(1, 1);

    const int wm = wid * 16;
    float acc[8][4];
#pragma unroll
    for (int j = 0; j < 8; j++)
#pragma unroll
        for (int e = 0; e < 4; e++) acc[j][e] = 0.0f;
    float mi0 = -INFINITY, mi1 = -INFINITY, li0 = 0.0f, li1 = 0.0f;
    uint32_t qf[4][4];

    int cur = 0;
    for (int kt = 0; kt < nkt; kt++) {
        if (kt + 2 < nkt) {
            int nx = cur + 2; if (nx >= 3) nx -= 3;
            ISSUE_KV(kt + 2, nx);
            CP_WAIT(2);
        } else {
            CP_WAIT(0);
        }
        __syncthreads();

        if (kt == 0) {
#pragma unroll
            for (int ks = 0; ks < 4; ks++)
                ldm_x4(qf[ks],
                       sb + (wm + (lane & 15)) * ASTR + ks * 32 + (lane >> 4) * 16);
        }

        const uint32_t stg = sStage + (uint32_t)cur * ASTAGE;
        const int k0 = kt * 64;
        const bool skip = (k0 > q0 + wm + 15);
        if (!skip) {
            // ---- scores S = Q K^T (fp16 x fp16) ----
            float s[8][4];
#pragma unroll
            for (int j = 0; j < 8; j++)
#pragma unroll
                for (int e = 0; e < 4; e++) s[j][e] = 0.0f;
#pragma unroll
            for (int ks = 0; ks < 4; ks++) {
#pragma unroll
                for (int nt = 0; nt < 4; nt++) {
                    uint32_t r4[4];
                    ldm_x4(r4, stg + (nt * 16 + (lane & 15)) * ASTR +
                               ks * 32 + (lane >> 4) * 16);
                    uint32_t b0[2] = {r4[0], r4[2]}, b1[2] = {r4[1], r4[3]};
                    mma16816h(s[nt * 2],     qf[ks], b0);
                    mma16816h(s[nt * 2 + 1], qf[ks], b1);
                }
            }

            // ---- mask + scale ----
            const int row0 = q0 + wm + (lane >> 2);
            const int row1 = row0 + 8;
            const bool needmask = (k0 + 63 > q0 + wm);
            if (needmask) {
#pragma unroll
                for (int j = 0; j < 8; j++) {
                    const int cbase = k0 + j * 8 + (lane & 3) * 2;
                    s[j][0] = (cbase     <= row0) ? s[j][0] * 0.125f : -INFINITY;
                    s[j][1] = (cbase + 1 <= row0) ? s[j][1] * 0.125f : -INFINITY;
                    s[j][2] = (cbase     <= row1) ? s[j][2] * 0.125f : -INFINITY;
                    s[j][3] = (cbase + 1 <= row1) ? s[j][3] * 0.125f : -INFINITY;
                }
            } else {
#pragma unroll
                for (int j = 0; j < 8; j++)
#pragma unroll
                    for (int e = 0; e < 4; e++) s[j][e] *= 0.125f;
            }

            // ---- online softmax ----
            float tm0 = -INFINITY, tm1 = -INFINITY;
#pragma unroll
            for (int j = 0; j < 8; j++) {
                tm0 = fmaxf(tm0, fmaxf(s[j][0], s[j][1]));
                tm1 = fmaxf(tm1, fmaxf(s[j][2], s[j][3]));
            }
            tm0 = fmaxf(tm0, __shfl_xor_sync(0xffffffffu, tm0, 1));
            tm0 = fmaxf(tm0, __shfl_xor_sync(0xffffffffu, tm0, 2));
            tm1 = fmaxf(tm1, __shfl_xor_sync(0xffffffffu, tm1, 1));
            tm1 = fmaxf(tm1, __shfl_xor_sync(0xffffffffu, tm1, 2));
            const float mn0 = fmaxf(mi0, tm0);
            const float mn1 = fmaxf(mi1, tm1);
            const float c0 = __expf(mi0 - mn0);
            const float c1 = __expf(mi1 - mn1);
            float ls0 = 0.0f, ls1 = 0.0f;
#pragma unroll
            for (int j = 0; j < 8; j++) {
                s[j][0] = __expf(s[j][0] - mn0);
                s[j][1] = __expf(s[j][1] - mn0);
                s[j][2] = __expf(s[j][2] - mn1);
                s[j][3] = __expf(s[j][3] - mn1);
                ls0 += s[j][0] + s[j][1];
                ls1 += s[j][2] + s[j][3];
            }
            ls0 += __shfl_xor_sync(0xffffffffu, ls0, 1);
            ls0 += __shfl_xor_sync(0xffffffffu, ls0, 2);
            ls1 += __shfl_xor_sync(0xffffffffu, ls1, 1);
            ls1 += __shfl_xor_sync(0xffffffffu, ls1, 2);
            li0 = li0 * c0 + ls0;
            li1 = li1 * c1 + ls1;
            mi0 = mn0; mi1 = mn1;
#pragma unroll
            for (int j = 0; j < 8; j++) {
                acc[j][0] *= c0; acc[j][1] *= c0;
                acc[j][2] *= c1; acc[j][3] *= c1;
            }

            // ---- PV: single fp16 MMA per fragment ----
#pragma unroll
            for (int ks = 0; ks < 4; ks++) {
                uint32_t A[4];
                A[0] = packh2(s[2 * ks][0],     s[2 * ks][1]);
                A[1] = packh2(s[2 * ks][2],     s[2 * ks][3]);
                A[2] = packh2(s[2 * ks + 1][0], s[2 * ks + 1][1]);
                A[3] = packh2(s[2 * ks + 1][2], s[2 * ks + 1][3]);
#pragma unroll
                for (int dvt = 0; dvt < 4; dvt++) {
                    uint32_t r4[4];
                    ldm_x4_t(r4, stg + AKV_BYTES +
                                 (ks * 16 + (lane & 15)) * ASTR +
                                 dvt * 32 + (lane >> 4) * 16);
                    uint32_t vba[2] = {r4[0], r4[1]}, vbb[2] = {r4[2], r4[3]};
                    mma16816h(acc[2 * dvt],     A, vba);
                    mma16816h(acc[2 * dvt + 1], A, vbb);
                }
            }
        }
        __syncthreads();
        if (++cur == 3) cur = 0;
    }

    // ---- epilogue: O rows -> fp16 gOh ----
    const float inv0 = 1.0f / li0;
    const float inv1 = 1.0f / li1;
    const int row0 = q0 + wm + (lane >> 2);
    const int row1 = row0 + 8;
    const size_t ob0 = ((size_t)b * SEQ + row0) * DIM + h * DH;
    const size_t ob1 = ((size_t)b * SEQ + row1) * DIM + h * DH;
#pragma unroll
    for (int j = 0; j < 8; j++) {
        const int dv = j * 8 + (lane & 3) * 2;
        *(uint32_t*)(gOh + ob0 + dv) = packh2(acc[j][0] * inv0, acc[j][1] * inv0);
        *(uint32_t*)(gOh + ob1 + dv) = packh2(acc[j][2] * inv1, acc[j][3] * inv1);
    }
}

// ---------------------------------------------------------------------------
// kernel_launch
// ---------------------------------------------------------------------------
extern "C" void kernel_launch(void* const* d_in, const int* in_sizes, int n_in,
                              void* d_out, int out_size) {
    const float* x  = (const float*)d_in[0];
    // d_in[1] = causal mask (structure known, unused)
    const float* Wq = (const float*)d_in[2];
    const float* Wk = (const float*)d_in[3];
    const float* Wv = (const float*)d_in[4];
    const float* Wo = (const float*)d_in[5];
    float* out = (float*)d_out;

    cudaFuncSetAttribute(hmma_gemm<0>, cudaFuncAttributeMaxDynamicSharedMemorySize, SMEM_DYN);
    cudaFuncSetAttribute(hmma_gemm<1>, cudaFuncAttributeMaxDynamicSharedMemorySize, SMEM_DYN);
    cudaFuncSetAttribute(attn_mma, cudaFuncAttributeMaxDynamicSharedMemorySize, ATTN_SMEM);

    conv_x_kernel<<<(MTOT * DIM / 4) / 256, 256>>>(x);
    prep_w_kernel<<<dim3(DIM / 32, DIM / 32, 4), 256>>>(Wq, Wk, Wv, Wo);

    hmma_gemm<1><<<dim3(DIM / 128, MTOT / 128, 3), 256, SMEM_DYN>>>(nullptr);

    attn_mma<<<dim3(SEQ / 128, HEADS, BB), 256, ATTN_SMEM>>>();

    hmma_gemm<0><<<dim3(DIM / 128, MTOT / 128, 1), 256, SMEM_DYN>>>(out);
}